// round 2
// baseline (speedup 1.0000x reference)
#include <cuda_runtime.h>
#include <math.h>
#include <stdint.h>

#define NN 30000
#define EE 480000
#define EN (EE + NN)
#define NF 128
#define SLOPE 0.02f
#define TILE 64

// ---------------- scratch (device globals; no allocation allowed) ----------
__device__ int   g_cnt[NN];
__device__ float g_dinv[NN];
__device__ int   g_rowptr[NN + 1];
__device__ int   g_fill[NN];
__device__ int   g_csr_src[EN];
__device__ float g_csr_w[EN];
__device__ float g_bufA[NN * NF];
__device__ float g_bufB[NN * NF];
__device__ int   g_is64;

// ---------------- packed f32x2 helpers --------------------------------------
__device__ __forceinline__ unsigned long long pack2(float a) {
    unsigned long long r;
    asm("mov.b64 %0, {%1, %1};" : "=l"(r) : "f"(a));
    return r;
}
__device__ __forceinline__ void ffma2(unsigned long long& d,
                                      unsigned long long a,
                                      unsigned long long b) {
    asm("fma.rn.f32x2 %0, %1, %2, %0;" : "+l"(d) : "l"(a), "l"(b));
}
__device__ __forceinline__ void unpack2(unsigned long long v, float& lo, float& hi) {
    asm("mov.b64 {%0, %1}, %2;" : "=f"(lo), "=f"(hi) : "l"(v));
}

// ---------------- edge-index dtype detection (warp-parallel) ----------------
__global__ void k_detect(const unsigned int* __restrict__ w) {
    // int64 edge values < 2^31 => every odd 32-bit word of first 128 entries is 0.
    int lane = threadIdx.x;
    unsigned bad = 0;
    for (int i = lane; i < 128; i += 32) bad |= w[2 * i + 1];
    bad = __reduce_or_sync(0xffffffffu, bad);
    if (lane == 0) g_is64 = (bad == 0u);
}

__device__ __forceinline__ int edge_at(const void* ei, int idx) {
    return g_is64 ? (int)((const long long*)ei)[idx]
                  : ((const int*)ei)[idx];
}

// ---------------- graph preprocessing ---------------------------------------
__global__ void k_init_cnt() {
    int i = blockIdx.x * blockDim.x + threadIdx.x;
    if (i < NN) g_cnt[i] = 1;  // self-loop
}

__global__ void k_count(const void* __restrict__ ei) {
    int e = blockIdx.x * blockDim.x + threadIdx.x;
    if (e < EE) atomicAdd(&g_cnt[edge_at(ei, EE + e)], 1);
}

__global__ void k_dinv() {
    int i = blockIdx.x * blockDim.x + threadIdx.x;
    if (i < NN) g_dinv[i] = rsqrtf((float)g_cnt[i]);
}

// single-pass scan: 1024 threads x 30 contiguous elements each
__global__ void k_scan() {
    __shared__ int sh[1024];
    const int tid = threadIdx.x;
    const int C = 30;  // 1024*30 = 30720 >= NN
    int base = tid * C;
    int s = 0;
    #pragma unroll
    for (int i = 0; i < C; i++) {
        int idx = base + i;
        if (idx < NN) s += g_cnt[idx];
    }
    sh[tid] = s;
    __syncthreads();
    #pragma unroll
    for (int d = 1; d < 1024; d <<= 1) {
        int t = (tid >= d) ? sh[tid - d] : 0;
        __syncthreads();
        sh[tid] += t;
        __syncthreads();
    }
    int run = sh[tid] - s;  // exclusive prefix
    #pragma unroll
    for (int i = 0; i < C; i++) {
        int idx = base + i;
        if (idx < NN) {
            g_rowptr[idx] = run;
            g_fill[idx]   = run;
            run += g_cnt[idx];
        }
    }
    if (tid == 1023) g_rowptr[NN] = sh[1023];
}

__global__ void k_fill(const void* __restrict__ ei) {
    int e = blockIdx.x * blockDim.x + threadIdx.x;
    if (e < EE) {
        int s = edge_at(ei, e);
        int d = edge_at(ei, EE + e);
        int pos = atomicAdd(&g_fill[d], 1);
        g_csr_src[pos] = s;
        g_csr_w[pos]   = g_dinv[s] * g_dinv[d];
    } else if (e < EN) {
        int i = e - EE;
        int pos = atomicAdd(&g_fill[i], 1);
        float di = g_dinv[i];
        g_csr_src[pos] = i;
        g_csr_w[pos]   = di * di;
    }
}

// ---------------- fused layer: out = leaky( (A X) @ W + b ) -----------------
// X: [NN, K] (already post-activation where applicable), W: [K, 128], out: [NN, 128].
// Block: 256 threads, 64-node tile. Phase 1: weighted gather-aggregate into smem
// (L2-bound). Phase 2: register-blocked FFMA2 GEMM against W in smem (fma-bound).
template<int K>
__global__ void __launch_bounds__(256, 2) k_fused(const float* __restrict__ X,
                                                  const float* __restrict__ W,
                                                  const float* __restrict__ bias,
                                                  float* __restrict__ out) {
    extern __shared__ float sm[];
    float* sh_w = sm;           // K * 128
    float* sh_h = sm + K * NF;  // TILE * K
    const int tid = threadIdx.x;
    const int node0 = blockIdx.x * TILE;

    // stage W
    {
        const float4* Wv = (const float4*)W;
        float4* Sv = (float4*)sh_w;
        #pragma unroll
        for (int i = 0; i < (K * NF / 4) / 256; i++)
            Sv[tid + i * 256] = Wv[tid + i * 256];
    }

    // phase 1: aggregation. 8 warps x 8 nodes, lane covers K/32 floats.
    const int warp = tid >> 5, lane = tid & 31;
    for (int r = 0; r < 8; r++) {
        const int row = warp * 8 + r;
        const int n = node0 + row;
        if constexpr (K == 128) {
            float4 acc = make_float4(0.f, 0.f, 0.f, 0.f);
            if (n < NN) {
                int beg = g_rowptr[n], end = g_rowptr[n + 1];
                int j = beg;
                for (; j + 1 < end; j += 2) {
                    int   s0 = g_csr_src[j],   s1 = g_csr_src[j + 1];
                    float w0 = g_csr_w[j],     w1 = g_csr_w[j + 1];
                    float4 v0 = __ldg((const float4*)(X + (size_t)s0 * K + lane * 4));
                    float4 v1 = __ldg((const float4*)(X + (size_t)s1 * K + lane * 4));
                    acc.x += w0 * v0.x + w1 * v1.x;
                    acc.y += w0 * v0.y + w1 * v1.y;
                    acc.z += w0 * v0.z + w1 * v1.z;
                    acc.w += w0 * v0.w + w1 * v1.w;
                }
                if (j < end) {
                    int s = g_csr_src[j]; float w = g_csr_w[j];
                    float4 v = __ldg((const float4*)(X + (size_t)s * K + lane * 4));
                    acc.x += w * v.x; acc.y += w * v.y;
                    acc.z += w * v.z; acc.w += w * v.w;
                }
            }
            *(float4*)&sh_h[row * K + lane * 4] = acc;
        } else {
            float2 acc = make_float2(0.f, 0.f);
            if (n < NN) {
                int beg = g_rowptr[n], end = g_rowptr[n + 1];
                int j = beg;
                for (; j + 1 < end; j += 2) {
                    int   s0 = g_csr_src[j],   s1 = g_csr_src[j + 1];
                    float w0 = g_csr_w[j],     w1 = g_csr_w[j + 1];
                    float2 v0 = __ldg((const float2*)(X + (size_t)s0 * K + lane * 2));
                    float2 v1 = __ldg((const float2*)(X + (size_t)s1 * K + lane * 2));
                    acc.x += w0 * v0.x + w1 * v1.x;
                    acc.y += w0 * v0.y + w1 * v1.y;
                }
                if (j < end) {
                    int s = g_csr_src[j]; float w = g_csr_w[j];
                    float2 v = __ldg((const float2*)(X + (size_t)s * K + lane * 2));
                    acc.x += w * v.x; acc.y += w * v.y;
                }
            }
            *(float2*)&sh_h[row * K + lane * 2] = acc;
        }
    }
    __syncthreads();

    // phase 2: GEMM. thread = 4 nodes x 8 outs, FFMA2 accumulators.
    const int ng = (tid >> 4) * 4;    // node within tile: 0..60
    const int og = (tid & 15) * 8;    // out col: 0..120
    unsigned long long acc[4][4] = {};

    #pragma unroll 4
    for (int k = 0; k < K; k++) {
        ulonglong2 wa = *(const ulonglong2*)&sh_w[k * NF + og];
        ulonglong2 wb = *(const ulonglong2*)&sh_w[k * NF + og + 4];
        #pragma unroll
        for (int i = 0; i < 4; i++) {
            unsigned long long hh = pack2(sh_h[(ng + i) * K + k]);
            ffma2(acc[i][0], hh, wa.x);
            ffma2(acc[i][1], hh, wa.y);
            ffma2(acc[i][2], hh, wb.x);
            ffma2(acc[i][3], hh, wb.y);
        }
    }

    float4 b0 = __ldg((const float4*)(bias + og));
    float4 b1 = __ldg((const float4*)(bias + og + 4));
    const float bv[8] = {b0.x, b0.y, b0.z, b0.w, b1.x, b1.y, b1.z, b1.w};

    #pragma unroll
    for (int i = 0; i < 4; i++) {
        int n = node0 + ng + i;
        if (n >= NN) continue;
        float o[8];
        #pragma unroll
        for (int j = 0; j < 4; j++) unpack2(acc[i][j], o[2 * j], o[2 * j + 1]);
        #pragma unroll
        for (int j = 0; j < 8; j++) {
            float v = o[j] + bv[j];
            o[j] = v > 0.f ? v : v * SLOPE;   // stored post-activation
        }
        *(float4*)(out + (size_t)n * NF + og)     = make_float4(o[0], o[1], o[2], o[3]);
        *(float4*)(out + (size_t)n * NF + og + 4) = make_float4(o[4], o[5], o[6], o[7]);
    }
}

// ---------------- output head -----------------------------------------------
// P[n,0:3] = H[n,:] @ Wout[128,3]   (H already post-activation; one warp/node)
__global__ void k_gemm3(const float* __restrict__ H, const float* __restrict__ W,
                        float* __restrict__ out) {
    int n = (blockIdx.x * blockDim.x + threadIdx.x) >> 5;
    if (n >= NN) return;
    int lane = threadIdx.x & 31;
    float4 h = *(const float4*)(H + (size_t)n * NF + lane * 4);
    float hv[4] = {h.x, h.y, h.z, h.w};
    float a0 = 0.f, a1 = 0.f, a2 = 0.f;
    #pragma unroll
    for (int j = 0; j < 4; j++) {
        int k = lane * 4 + j;
        a0 += hv[j] * __ldg(W + k * 3 + 0);
        a1 += hv[j] * __ldg(W + k * 3 + 1);
        a2 += hv[j] * __ldg(W + k * 3 + 2);
    }
    #pragma unroll
    for (int o = 16; o > 0; o >>= 1) {
        a0 += __shfl_down_sync(0xffffffffu, a0, o);
        a1 += __shfl_down_sync(0xffffffffu, a1, o);
        a2 += __shfl_down_sync(0xffffffffu, a2, o);
    }
    if (lane == 0) {
        out[n * 3 + 0] = a0;
        out[n * 3 + 1] = a1;
        out[n * 3 + 2] = a2;
    }
}

// out[n] = tanh( (A P)[n] + bout ) * 0.5
__global__ void k_agg3(const float* __restrict__ T, const float* __restrict__ bout,
                       float* __restrict__ out) {
    int n = (blockIdx.x * blockDim.x + threadIdx.x) >> 5;
    if (n >= NN) return;
    int lane = threadIdx.x & 31;
    int beg = g_rowptr[n], end = g_rowptr[n + 1];
    float a0 = 0.f, a1 = 0.f, a2 = 0.f;
    for (int j = beg + lane; j < end; j += 32) {
        int s = g_csr_src[j]; float w = g_csr_w[j];
        a0 += w * __ldg(T + s * 3 + 0);
        a1 += w * __ldg(T + s * 3 + 1);
        a2 += w * __ldg(T + s * 3 + 2);
    }
    #pragma unroll
    for (int o = 16; o > 0; o >>= 1) {
        a0 += __shfl_down_sync(0xffffffffu, a0, o);
        a1 += __shfl_down_sync(0xffffffffu, a1, o);
        a2 += __shfl_down_sync(0xffffffffu, a2, o);
    }
    if (lane == 0) {
        out[n * 3 + 0] = tanhf(a0 + __ldg(bout + 0)) * 0.5f;
        out[n * 3 + 1] = tanhf(a1 + __ldg(bout + 1)) * 0.5f;
        out[n * 3 + 2] = tanhf(a2 + __ldg(bout + 2)) * 0.5f;
    }
}

// ---------------- launch -----------------------------------------------------
extern "C" void kernel_launch(void* const* d_in, const int* in_sizes, int n_in,
                              void* d_out, int out_size) {
    const float* x    = (const float*)d_in[0];
    const void*  ei   = d_in[1];
    const float* W0   = (const float*)d_in[2];
    const float* b0   = (const float*)d_in[3];
    const float* Wh   = (const float*)d_in[4];
    const float* bh   = (const float*)d_in[5];
    const float* Wout = (const float*)d_in[6];
    const float* bout = (const float*)d_in[7];
    float* out = (float*)d_out;

    void *pA, *pB;
    cudaGetSymbolAddress(&pA, g_bufA);
    cudaGetSymbolAddress(&pB, g_bufB);
    float* A = (float*)pA;
    float* B = (float*)pB;

    const int SMEM64  = (64 * NF + TILE * 64) * 4;    // 48 KB
    const int SMEM128 = (128 * NF + TILE * 128) * 4;  // 96 KB
    cudaFuncSetAttribute(k_fused<64>,  cudaFuncAttributeMaxDynamicSharedMemorySize, SMEM64);
    cudaFuncSetAttribute(k_fused<128>, cudaFuncAttributeMaxDynamicSharedMemorySize, SMEM128);

    // graph preprocessing
    k_detect<<<1, 32>>>((const unsigned int*)ei);
    k_init_cnt<<<(NN + 255) / 256, 256>>>();
    k_count<<<(EE + 255) / 256, 256>>>(ei);
    k_dinv<<<(NN + 255) / 256, 256>>>();
    k_scan<<<1, 1024>>>();
    k_fill<<<(EN + 255) / 256, 256>>>(ei);

    const int tileBlocks = (NN + TILE - 1) / TILE;   // 469
    const int warpBlocks = (NN * 32 + 255) / 256;    // one warp per node

    // layer 0: B = leaky( (A x) @ W0 + b0 )
    k_fused<64><<<tileBlocks, 256, SMEM64>>>(x, W0, b0, B);

    // 6 hidden layers (ping-pong): h = leaky( (A h) @ Wh[i] + bh[i] )
    const float* src = B;
    float* dst = A;
    for (int i = 0; i < 6; i++) {
        k_fused<128><<<tileBlocks, 256, SMEM128>>>(src, Wh + (size_t)i * NF * NF,
                                                   bh + (size_t)i * NF, dst);
        const float* t = src; src = dst; dst = (float*)t;
    }
    // after 6 layers, h lives in `src` (== B)

    // output: out = tanh( A (h @ Wout) + bout ) * 0.5
    k_gemm3<<<warpBlocks, 256>>>(src, Wout, dst);
    k_agg3<<<warpBlocks, 256>>>(dst, bout, out);
}

// round 3
// speedup vs baseline: 1.0463x; 1.0463x over previous
#include <cuda_runtime.h>
#include <math.h>
#include <stdint.h>

#define NN 30000
#define EE 480000
#define EN (EE + NN)
#define NF 128
#define SLOPE 0.02f

// ---------------- scratch (device globals; no allocation allowed) ----------
__device__ int   g_cnt[NN];
__device__ float g_dinv[NN];
__device__ int   g_rowptr[NN + 1];
__device__ int   g_fill[NN];
__device__ int   g_csr_src[EN];
__device__ float g_csr_w[EN];
__device__ float g_bufA[NN * NF];
__device__ float g_bufB[NN * NF];
__device__ int   g_is64;

// ---------------- packed f32x2 helpers --------------------------------------
__device__ __forceinline__ unsigned long long pack2(float a) {
    unsigned long long r;
    asm("mov.b64 %0, {%1, %1};" : "=l"(r) : "f"(a));
    return r;
}
__device__ __forceinline__ void ffma2(unsigned long long& d,
                                      unsigned long long a,
                                      unsigned long long b) {
    asm("fma.rn.f32x2 %0, %1, %2, %0;" : "+l"(d) : "l"(a), "l"(b));
}
__device__ __forceinline__ void unpack2(unsigned long long v, float& lo, float& hi) {
    asm("mov.b64 {%0, %1}, %2;" : "=f"(lo), "=f"(hi) : "l"(v));
}

// ---------------- edge-index dtype detection (warp-parallel) ----------------
__global__ void k_detect(const unsigned int* __restrict__ w) {
    // int64 edge values < 2^31 => every odd 32-bit word of first 128 entries is 0.
    int lane = threadIdx.x;
    unsigned bad = 0;
    for (int i = lane; i < 128; i += 32) bad |= w[2 * i + 1];
    #pragma unroll
    for (int o = 16; o > 0; o >>= 1) bad |= __shfl_xor_sync(0xffffffffu, bad, o);
    if (lane == 0) g_is64 = (bad == 0u);
}

__device__ __forceinline__ int edge_at(const void* ei, int idx) {
    return g_is64 ? (int)((const long long*)ei)[idx]
                  : ((const int*)ei)[idx];
}

// ---------------- graph preprocessing ---------------------------------------
__global__ void k_init_cnt() {
    int i = blockIdx.x * blockDim.x + threadIdx.x;
    if (i < NN) g_cnt[i] = 1;  // self-loop
}

__global__ void k_count(const void* __restrict__ ei) {
    int e = blockIdx.x * blockDim.x + threadIdx.x;
    if (e < EE) atomicAdd(&g_cnt[edge_at(ei, EE + e)], 1);
}

// single-pass scan: 1024 threads x 30 contiguous elements each; also emits dinv
__global__ void k_scan() {
    __shared__ int sh[1024];
    const int tid = threadIdx.x;
    const int C = 30;  // 1024*30 = 30720 >= NN
    int base = tid * C;
    int cnt[C];
    int s = 0;
    #pragma unroll
    for (int i = 0; i < C; i++) {
        int idx = base + i;
        int v = (idx < NN) ? g_cnt[idx] : 0;
        cnt[i] = v;
        s += v;
        if (idx < NN) g_dinv[idx] = rsqrtf((float)v);
    }
    sh[tid] = s;
    __syncthreads();
    #pragma unroll
    for (int d = 1; d < 1024; d <<= 1) {
        int t = (tid >= d) ? sh[tid - d] : 0;
        __syncthreads();
        sh[tid] += t;
        __syncthreads();
    }
    int run = sh[tid] - s;  // exclusive prefix
    #pragma unroll
    for (int i = 0; i < C; i++) {
        int idx = base + i;
        if (idx < NN) {
            g_rowptr[idx] = run;
            g_fill[idx]   = run;
            run += cnt[i];
        }
    }
    if (tid == 1023) g_rowptr[NN] = sh[1023];
}

__global__ void k_fill(const void* __restrict__ ei) {
    int e = blockIdx.x * blockDim.x + threadIdx.x;
    if (e < EE) {
        int s = edge_at(ei, e);
        int d = edge_at(ei, EE + e);
        int pos = atomicAdd(&g_fill[d], 1);
        g_csr_src[pos] = s;
        g_csr_w[pos]   = g_dinv[s] * g_dinv[d];
    } else if (e < EN) {
        int i = e - EE;
        int pos = atomicAdd(&g_fill[i], 1);
        float di = g_dinv[i];
        g_csr_src[pos] = i;
        g_csr_w[pos]   = di * di;
    }
}

// ---------------- aggregation kernels (one warp per node, R1-proven) --------
__global__ void k_agg64(const float* __restrict__ X, float* __restrict__ out) {
    int n = (blockIdx.x * blockDim.x + threadIdx.x) >> 5;
    if (n >= NN) return;
    int lane = threadIdx.x & 31;
    int beg = g_rowptr[n], end = g_rowptr[n + 1];
    float2 acc = make_float2(0.f, 0.f);
    int j = beg;
    for (; j + 3 < end; j += 4) {
        int   s0 = g_csr_src[j],   s1 = g_csr_src[j+1],
              s2 = g_csr_src[j+2], s3 = g_csr_src[j+3];
        float w0 = g_csr_w[j],   w1 = g_csr_w[j+1],
              w2 = g_csr_w[j+2], w3 = g_csr_w[j+3];
        float2 v0 = __ldg((const float2*)(X + s0 * 64 + lane * 2));
        float2 v1 = __ldg((const float2*)(X + s1 * 64 + lane * 2));
        float2 v2 = __ldg((const float2*)(X + s2 * 64 + lane * 2));
        float2 v3 = __ldg((const float2*)(X + s3 * 64 + lane * 2));
        acc.x += w0*v0.x + w1*v1.x + w2*v2.x + w3*v3.x;
        acc.y += w0*v0.y + w1*v1.y + w2*v2.y + w3*v3.y;
    }
    for (; j < end; j++) {
        int s = g_csr_src[j]; float w = g_csr_w[j];
        float2 v = __ldg((const float2*)(X + s * 64 + lane * 2));
        acc.x += w * v.x; acc.y += w * v.y;
    }
    *(float2*)(out + n * 64 + lane * 2) = acc;
}

__global__ void k_agg128(const float* __restrict__ T, const float* __restrict__ bias,
                         float* __restrict__ out) {
    int n = (blockIdx.x * blockDim.x + threadIdx.x) >> 5;
    if (n >= NN) return;
    int lane = threadIdx.x & 31;
    int beg = g_rowptr[n], end = g_rowptr[n + 1];
    float4 acc = make_float4(0.f, 0.f, 0.f, 0.f);
    int j = beg;
    for (; j + 3 < end; j += 4) {
        int   s0 = g_csr_src[j],   s1 = g_csr_src[j+1],
              s2 = g_csr_src[j+2], s3 = g_csr_src[j+3];
        float w0 = g_csr_w[j],   w1 = g_csr_w[j+1],
              w2 = g_csr_w[j+2], w3 = g_csr_w[j+3];
        float4 v0 = __ldg((const float4*)(T + s0 * NF + lane * 4));
        float4 v1 = __ldg((const float4*)(T + s1 * NF + lane * 4));
        float4 v2 = __ldg((const float4*)(T + s2 * NF + lane * 4));
        float4 v3 = __ldg((const float4*)(T + s3 * NF + lane * 4));
        acc.x += w0*v0.x + w1*v1.x + w2*v2.x + w3*v3.x;
        acc.y += w0*v0.y + w1*v1.y + w2*v2.y + w3*v3.y;
        acc.z += w0*v0.z + w1*v1.z + w2*v2.z + w3*v3.z;
        acc.w += w0*v0.w + w1*v1.w + w2*v2.w + w3*v3.w;
    }
    for (; j < end; j++) {
        int s = g_csr_src[j]; float w = g_csr_w[j];
        float4 v = __ldg((const float4*)(T + s * NF + lane * 4));
        acc.x += w*v.x; acc.y += w*v.y; acc.z += w*v.z; acc.w += w*v.w;
    }
    float4 b = __ldg((const float4*)(bias + lane * 4));
    acc.x += b.x; acc.y += b.y; acc.z += b.z; acc.w += b.w;
    *(float4*)(out + n * NF + lane * 4) = acc;
}

__global__ void k_agg3(const float* __restrict__ T, const float* __restrict__ bout,
                       float* __restrict__ out) {
    int n = (blockIdx.x * blockDim.x + threadIdx.x) >> 5;
    if (n >= NN) return;
    int lane = threadIdx.x & 31;
    int beg = g_rowptr[n], end = g_rowptr[n + 1];
    float a0 = 0.f, a1 = 0.f, a2 = 0.f;
    for (int j = beg + lane; j < end; j += 32) {
        int s = g_csr_src[j]; float w = g_csr_w[j];
        a0 += w * __ldg(T + s * 3 + 0);
        a1 += w * __ldg(T + s * 3 + 1);
        a2 += w * __ldg(T + s * 3 + 2);
    }
    #pragma unroll
    for (int o = 16; o > 0; o >>= 1) {
        a0 += __shfl_down_sync(0xffffffffu, a0, o);
        a1 += __shfl_down_sync(0xffffffffu, a1, o);
        a2 += __shfl_down_sync(0xffffffffu, a2, o);
    }
    if (lane == 0) {
        out[n * 3 + 0] = tanhf(a0 + __ldg(bout + 0)) * 0.5f;
        out[n * 3 + 1] = tanhf(a1 + __ldg(bout + 1)) * 0.5f;
        out[n * 3 + 2] = tanhf(a2 + __ldg(bout + 2)) * 0.5f;
    }
}

// ---------------- FFMA2 GEMM: out[N,128] = act(H[N,K]) @ W[K,128] (+ bias) --
// 64-node x 128-out tile, 256 threads, thread = 4 nodes x 8 outs.
// H staged to smem (activation on load), 4-k chunks held in registers so the
// inner loop is fma-pipe-bound (2 LDS.128 for W + 16 FFMA2 per k).
template<int K, bool ACT, bool BIAS>
__global__ void __launch_bounds__(256) k_gemm(const float* __restrict__ H,
                                              const float* __restrict__ W,
                                              const float* __restrict__ bias,
                                              float* __restrict__ out) {
    extern __shared__ float sm[];
    float* sh_w = sm;           // K * 128 floats
    float* sh_h = sm + K * NF;  // 64 * K floats
    const int tid = threadIdx.x;
    const int node0 = blockIdx.x * 64;

    // stage W: K*128/4 float4 over 256 threads
    {
        const float4* Wv = (const float4*)W;
        float4* Sv = (float4*)sh_w;
        #pragma unroll
        for (int i = 0; i < (K * NF / 4) / 256; i++)
            Sv[tid + i * 256] = Wv[tid + i * 256];
    }
    // stage H (64 x K) with optional activation
    {
        #pragma unroll
        for (int i = 0; i < (64 * K / 4) / 256; i++) {
            int idx = tid + i * 256;
            int nd = idx / (K / 4);
            int kg = idx % (K / 4);
            int node = node0 + nd;
            float4 v = make_float4(0.f, 0.f, 0.f, 0.f);
            if (node < NN)
                v = __ldg((const float4*)(H + (size_t)node * K + kg * 4));
            if (ACT) {
                v.x = v.x > 0.f ? v.x : v.x * SLOPE;
                v.y = v.y > 0.f ? v.y : v.y * SLOPE;
                v.z = v.z > 0.f ? v.z : v.z * SLOPE;
                v.w = v.w > 0.f ? v.w : v.w * SLOPE;
            }
            *(float4*)&sh_h[nd * K + kg * 4] = v;
        }
    }
    __syncthreads();

    const int og = (tid & 15) * 8;   // out col 0..120
    const int ng = (tid >> 4) * 4;   // node 0..60
    unsigned long long acc[4][4] = {};

    for (int k0 = 0; k0 < K; k0 += 4) {
        float4 hv[4];
        #pragma unroll
        for (int i = 0; i < 4; i++)
            hv[i] = *(const float4*)&sh_h[(ng + i) * K + k0];
        #pragma unroll
        for (int kk = 0; kk < 4; kk++) {
            ulonglong2 wa = *(const ulonglong2*)&sh_w[(k0 + kk) * NF + og];
            ulonglong2 wb = *(const ulonglong2*)&sh_w[(k0 + kk) * NF + og + 4];
            #pragma unroll
            for (int i = 0; i < 4; i++) {
                unsigned long long hh = pack2(((const float*)&hv[i])[kk]);
                ffma2(acc[i][0], hh, wa.x);
                ffma2(acc[i][1], hh, wa.y);
                ffma2(acc[i][2], hh, wb.x);
                ffma2(acc[i][3], hh, wb.y);
            }
        }
    }

    float bv[8] = {0.f, 0.f, 0.f, 0.f, 0.f, 0.f, 0.f, 0.f};
    if (BIAS) {
        float4 b0 = __ldg((const float4*)(bias + og));
        float4 b1 = __ldg((const float4*)(bias + og + 4));
        bv[0]=b0.x; bv[1]=b0.y; bv[2]=b0.z; bv[3]=b0.w;
        bv[4]=b1.x; bv[5]=b1.y; bv[6]=b1.z; bv[7]=b1.w;
    }
    #pragma unroll
    for (int i = 0; i < 4; i++) {
        int n = node0 + ng + i;
        if (n >= NN) continue;
        float o[8];
        #pragma unroll
        for (int j = 0; j < 4; j++) unpack2(acc[i][j], o[2 * j], o[2 * j + 1]);
        #pragma unroll
        for (int j = 0; j < 8; j++) o[j] += bv[j];
        *(float4*)(out + (size_t)n * NF + og)     = make_float4(o[0], o[1], o[2], o[3]);
        *(float4*)(out + (size_t)n * NF + og + 4) = make_float4(o[4], o[5], o[6], o[7]);
    }
}

// ---------------- output head -----------------------------------------------
__global__ void k_gemm3(const float* __restrict__ H, const float* __restrict__ W,
                        float* __restrict__ out) {
    int n = (blockIdx.x * blockDim.x + threadIdx.x) >> 5;
    if (n >= NN) return;
    int lane = threadIdx.x & 31;
    float4 h = *(const float4*)(H + (size_t)n * NF + lane * 4);
    h.x = h.x > 0.f ? h.x : h.x * SLOPE;
    h.y = h.y > 0.f ? h.y : h.y * SLOPE;
    h.z = h.z > 0.f ? h.z : h.z * SLOPE;
    h.w = h.w > 0.f ? h.w : h.w * SLOPE;
    float hv[4] = {h.x, h.y, h.z, h.w};
    float a0 = 0.f, a1 = 0.f, a2 = 0.f;
    #pragma unroll
    for (int j = 0; j < 4; j++) {
        int k = lane * 4 + j;
        a0 += hv[j] * __ldg(W + k * 3 + 0);
        a1 += hv[j] * __ldg(W + k * 3 + 1);
        a2 += hv[j] * __ldg(W + k * 3 + 2);
    }
    #pragma unroll
    for (int o = 16; o > 0; o >>= 1) {
        a0 += __shfl_down_sync(0xffffffffu, a0, o);
        a1 += __shfl_down_sync(0xffffffffu, a1, o);
        a2 += __shfl_down_sync(0xffffffffu, a2, o);
    }
    if (lane == 0) {
        out[n * 3 + 0] = a0;
        out[n * 3 + 1] = a1;
        out[n * 3 + 2] = a2;
    }
}

// ---------------- launch -----------------------------------------------------
extern "C" void kernel_launch(void* const* d_in, const int* in_sizes, int n_in,
                              void* d_out, int out_size) {
    const float* x    = (const float*)d_in[0];
    const void*  ei   = d_in[1];
    const float* W0   = (const float*)d_in[2];
    const float* b0   = (const float*)d_in[3];
    const float* Wh   = (const float*)d_in[4];
    const float* bh   = (const float*)d_in[5];
    const float* Wout = (const float*)d_in[6];
    const float* bout = (const float*)d_in[7];
    float* out = (float*)d_out;

    void *pA, *pB;
    cudaGetSymbolAddress(&pA, g_bufA);
    cudaGetSymbolAddress(&pB, g_bufB);
    float* A = (float*)pA;
    float* B = (float*)pB;

    const int SMEM64  = (64 * NF + 64 * 64) * 4;    // 48 KB
    const int SMEM128 = (128 * NF + 64 * 128) * 4;  // 96 KB
    cudaFuncSetAttribute(k_gemm<64, false, true>,
                         cudaFuncAttributeMaxDynamicSharedMemorySize, SMEM64);
    cudaFuncSetAttribute(k_gemm<128, true, false>,
                         cudaFuncAttributeMaxDynamicSharedMemorySize, SMEM128);

    // graph preprocessing
    k_detect<<<1, 32>>>((const unsigned int*)ei);
    k_init_cnt<<<(NN + 255) / 256, 256>>>();
    k_count<<<(EE + 255) / 256, 256>>>(ei);
    k_scan<<<1, 1024>>>();
    k_fill<<<(EN + 255) / 256, 256>>>(ei);

    const int tileBlocks = (NN + 63) / 64;        // 469
    const int warpBlocks = (NN * 32 + 255) / 256; // one warp per node

    // layer 0: B = (A x) @ W0 + b0
    k_agg64<<<warpBlocks, 256>>>(x, A);
    k_gemm<64, false, true><<<tileBlocks, 256, SMEM64>>>(A, W0, b0, B);

    // 6 hidden layers: h = A(leaky(h) @ Wh[i]) + bh[i]
    for (int i = 0; i < 6; i++) {
        k_gemm<128, true, false><<<tileBlocks, 256, SMEM128>>>(B, Wh + (size_t)i * NF * NF,
                                                               nullptr, A);
        k_agg128<<<warpBlocks, 256>>>(A, bh + (size_t)i * NF, B);
    }

    // output: out = tanh( A (leaky(h) @ Wout) + bout ) * 0.5
    k_gemm3<<<warpBlocks, 256>>>(B, Wout, A);
    k_agg3<<<warpBlocks, 256>>>(A, bout, out);
}

// round 4
// speedup vs baseline: 1.3017x; 1.2440x over previous
#include <cuda_runtime.h>
#include <math.h>
#include <stdint.h>

#define NN 30000
#define EE 480000
#define EN (EE + NN)
#define NF 128
#define SLOPE 0.02f

// ---------------- scratch (device globals; no allocation allowed) ----------
__device__ int   g_cnt[NN];
__device__ float g_dinv[NN];
__device__ int   g_rowptr[NN + 1];
__device__ int   g_fill[NN];
__device__ int   g_csr_src[EN];
__device__ float g_csr_w[EN];
__device__ float g_bufA[NN * NF];
__device__ float g_bufB[NN * NF];
__device__ int   g_is64;

// ---------------- edge-index dtype detection (warp-parallel) ----------------
__global__ void k_detect(const unsigned int* __restrict__ w) {
    // int64 edge values < 2^31 => every odd 32-bit word of first 128 entries is 0.
    int lane = threadIdx.x;
    unsigned bad = 0;
    for (int i = lane; i < 128; i += 32) bad |= w[2 * i + 1];
    #pragma unroll
    for (int o = 16; o > 0; o >>= 1) bad |= __shfl_xor_sync(0xffffffffu, bad, o);
    if (lane == 0) g_is64 = (bad == 0u);
}

__device__ __forceinline__ int edge_at(const void* ei, int idx) {
    return g_is64 ? (int)((const long long*)ei)[idx]
                  : ((const int*)ei)[idx];
}

// ---------------- graph preprocessing ---------------------------------------
__global__ void k_init_cnt() {
    int i = blockIdx.x * blockDim.x + threadIdx.x;
    if (i < NN) g_cnt[i] = 1;  // self-loop
}

__global__ void k_count(const void* __restrict__ ei) {
    int e = blockIdx.x * blockDim.x + threadIdx.x;
    if (e < EE) atomicAdd(&g_cnt[edge_at(ei, EE + e)], 1);
}

// smem-staged single-block scan (no register arrays -> no spills).
// Dynamic smem: NN + 1024 ints = 124 KB.
__global__ void k_scan() {
    extern __shared__ int sh[];
    int* shc = sh;        // counts [NN]
    int* shs = sh + NN;   // per-thread sums [1024]
    const int tid = threadIdx.x;

    for (int i = tid; i < NN; i += 1024) {
        int v = g_cnt[i];
        shc[i] = v;
        g_dinv[i] = rsqrtf((float)v);
    }
    __syncthreads();

    const int C = 30;  // 1024*30 = 30720 >= NN
    const int base = tid * C;
    int s = 0;
    #pragma unroll
    for (int i = 0; i < C; i++) {
        int idx = base + i;
        if (idx < NN) s += shc[idx];
    }
    shs[tid] = s;
    __syncthreads();
    for (int d = 1; d < 1024; d <<= 1) {
        int t = (tid >= d) ? shs[tid - d] : 0;
        __syncthreads();
        shs[tid] += t;
        __syncthreads();
    }
    int run = shs[tid] - s;  // exclusive prefix of this thread's chunk
    #pragma unroll
    for (int i = 0; i < C; i++) {
        int idx = base + i;
        if (idx < NN) {
            g_rowptr[idx] = run;
            g_fill[idx]   = run;
            run += shc[idx];
        }
    }
    if (tid == 1023) g_rowptr[NN] = shs[1023];
}

__global__ void k_fill(const void* __restrict__ ei) {
    int e = blockIdx.x * blockDim.x + threadIdx.x;
    if (e < EE) {
        int s = edge_at(ei, e);
        int d = edge_at(ei, EE + e);
        int pos = atomicAdd(&g_fill[d], 1);
        g_csr_src[pos] = s;
        g_csr_w[pos]   = g_dinv[s] * g_dinv[d];
    } else if (e < EN) {
        int i = e - EE;
        int pos = atomicAdd(&g_fill[i], 1);
        float di = g_dinv[i];
        g_csr_src[pos] = i;
        g_csr_w[pos]   = di * di;
    }
}

// ---------------- aggregation kernels (one warp per node, R1-proven) --------
__global__ void k_agg64(const float* __restrict__ X, float* __restrict__ out) {
    int n = (blockIdx.x * blockDim.x + threadIdx.x) >> 5;
    if (n >= NN) return;
    int lane = threadIdx.x & 31;
    int beg = g_rowptr[n], end = g_rowptr[n + 1];
    float2 acc = make_float2(0.f, 0.f);
    int j = beg;
    for (; j + 3 < end; j += 4) {
        int   s0 = g_csr_src[j],   s1 = g_csr_src[j+1],
              s2 = g_csr_src[j+2], s3 = g_csr_src[j+3];
        float w0 = g_csr_w[j],   w1 = g_csr_w[j+1],
              w2 = g_csr_w[j+2], w3 = g_csr_w[j+3];
        float2 v0 = __ldg((const float2*)(X + s0 * 64 + lane * 2));
        float2 v1 = __ldg((const float2*)(X + s1 * 64 + lane * 2));
        float2 v2 = __ldg((const float2*)(X + s2 * 64 + lane * 2));
        float2 v3 = __ldg((const float2*)(X + s3 * 64 + lane * 2));
        acc.x += w0*v0.x + w1*v1.x + w2*v2.x + w3*v3.x;
        acc.y += w0*v0.y + w1*v1.y + w2*v2.y + w3*v3.y;
    }
    for (; j < end; j++) {
        int s = g_csr_src[j]; float w = g_csr_w[j];
        float2 v = __ldg((const float2*)(X + s * 64 + lane * 2));
        acc.x += w * v.x; acc.y += w * v.y;
    }
    *(float2*)(out + n * 64 + lane * 2) = acc;
}

__global__ void k_agg128(const float* __restrict__ T, const float* __restrict__ bias,
                         float* __restrict__ out) {
    int n = (blockIdx.x * blockDim.x + threadIdx.x) >> 5;
    if (n >= NN) return;
    int lane = threadIdx.x & 31;
    int beg = g_rowptr[n], end = g_rowptr[n + 1];
    float4 acc = make_float4(0.f, 0.f, 0.f, 0.f);
    int j = beg;
    for (; j + 3 < end; j += 4) {
        int   s0 = g_csr_src[j],   s1 = g_csr_src[j+1],
              s2 = g_csr_src[j+2], s3 = g_csr_src[j+3];
        float w0 = g_csr_w[j],   w1 = g_csr_w[j+1],
              w2 = g_csr_w[j+2], w3 = g_csr_w[j+3];
        float4 v0 = __ldg((const float4*)(T + s0 * NF + lane * 4));
        float4 v1 = __ldg((const float4*)(T + s1 * NF + lane * 4));
        float4 v2 = __ldg((const float4*)(T + s2 * NF + lane * 4));
        float4 v3 = __ldg((const float4*)(T + s3 * NF + lane * 4));
        acc.x += w0*v0.x + w1*v1.x + w2*v2.x + w3*v3.x;
        acc.y += w0*v0.y + w1*v1.y + w2*v2.y + w3*v3.y;
        acc.z += w0*v0.z + w1*v1.z + w2*v2.z + w3*v3.z;
        acc.w += w0*v0.w + w1*v1.w + w2*v2.w + w3*v3.w;
    }
    for (; j < end; j++) {
        int s = g_csr_src[j]; float w = g_csr_w[j];
        float4 v = __ldg((const float4*)(T + s * NF + lane * 4));
        acc.x += w*v.x; acc.y += w*v.y; acc.z += w*v.z; acc.w += w*v.w;
    }
    float4 b = __ldg((const float4*)(bias + lane * 4));
    acc.x += b.x; acc.y += b.y; acc.z += b.z; acc.w += b.w;
    *(float4*)(out + n * NF + lane * 4) = acc;
}

__global__ void k_agg3(const float* __restrict__ T, const float* __restrict__ bout,
                       float* __restrict__ out) {
    int n = (blockIdx.x * blockDim.x + threadIdx.x) >> 5;
    if (n >= NN) return;
    int lane = threadIdx.x & 31;
    int beg = g_rowptr[n], end = g_rowptr[n + 1];
    float a0 = 0.f, a1 = 0.f, a2 = 0.f;
    for (int j = beg + lane; j < end; j += 32) {
        int s = g_csr_src[j]; float w = g_csr_w[j];
        a0 += w * __ldg(T + s * 3 + 0);
        a1 += w * __ldg(T + s * 3 + 1);
        a2 += w * __ldg(T + s * 3 + 2);
    }
    #pragma unroll
    for (int o = 16; o > 0; o >>= 1) {
        a0 += __shfl_down_sync(0xffffffffu, a0, o);
        a1 += __shfl_down_sync(0xffffffffu, a1, o);
        a2 += __shfl_down_sync(0xffffffffu, a2, o);
    }
    if (lane == 0) {
        out[n * 3 + 0] = tanhf(a0 + __ldg(bout + 0)) * 0.5f;
        out[n * 3 + 1] = tanhf(a1 + __ldg(bout + 1)) * 0.5f;
        out[n * 3 + 2] = tanhf(a2 + __ldg(bout + 2)) * 0.5f;
    }
}

// ---------------- dense GEMM (R1-proven): out = act(H) @ W (+ bias) ---------
// Tile: 32 nodes x 128 outs per 256-thread block; K chunked by 64.
template<int K, bool ACT, bool BIAS>
__global__ void __launch_bounds__(256) k_gemm(const float* __restrict__ H,
                                              const float* __restrict__ W,
                                              const float* __restrict__ bias,
                                              float* __restrict__ out) {
    __shared__ float sh_w[64][NF];   // 32 KB
    __shared__ float sh_h[32][64];   //  8 KB
    const int tid = threadIdx.x;
    const int node0 = blockIdx.x * 32;
    const int ng = (tid >> 5) * 4;   // node group within tile: 0..28
    const int fg = (tid & 31) * 4;   // output group: 0..124
    float acc[4][4] = {};

    for (int kc = 0; kc < K; kc += 64) {
        const float4* Wv = (const float4*)(W + kc * NF);
        #pragma unroll
        for (int i = 0; i < 8; i++)
            ((float4*)sh_w)[tid + i * 256] = Wv[tid + i * 256];
        #pragma unroll
        for (int i = 0; i < 2; i++) {
            int idx = tid + i * 256;
            int nd = idx >> 4;
            int kg = idx & 15;
            int node = node0 + nd;
            float4 v = make_float4(0.f, 0.f, 0.f, 0.f);
            if (node < NN)
                v = *(const float4*)(H + (size_t)node * K + kc + kg * 4);
            if (ACT) {
                v.x = v.x > 0.f ? v.x : v.x * SLOPE;
                v.y = v.y > 0.f ? v.y : v.y * SLOPE;
                v.z = v.z > 0.f ? v.z : v.z * SLOPE;
                v.w = v.w > 0.f ? v.w : v.w * SLOPE;
            }
            *(float4*)&sh_h[nd][kg * 4] = v;
        }
        __syncthreads();
        #pragma unroll
        for (int k = 0; k < 64; k++) {
            float4 wv = *(const float4*)&sh_w[k][fg];
            float h0 = sh_h[ng + 0][k];
            float h1 = sh_h[ng + 1][k];
            float h2 = sh_h[ng + 2][k];
            float h3 = sh_h[ng + 3][k];
            acc[0][0] += h0 * wv.x; acc[0][1] += h0 * wv.y;
            acc[0][2] += h0 * wv.z; acc[0][3] += h0 * wv.w;
            acc[1][0] += h1 * wv.x; acc[1][1] += h1 * wv.y;
            acc[1][2] += h1 * wv.z; acc[1][3] += h1 * wv.w;
            acc[2][0] += h2 * wv.x; acc[2][1] += h2 * wv.y;
            acc[2][2] += h2 * wv.z; acc[2][3] += h2 * wv.w;
            acc[3][0] += h3 * wv.x; acc[3][1] += h3 * wv.y;
            acc[3][2] += h3 * wv.z; acc[3][3] += h3 * wv.w;
        }
        __syncthreads();
    }

    float4 bv = make_float4(0.f, 0.f, 0.f, 0.f);
    if (BIAS) bv = *(const float4*)(bias + fg);
    #pragma unroll
    for (int i = 0; i < 4; i++) {
        int node = node0 + ng + i;
        if (node < NN) {
            float4 o;
            o.x = acc[i][0] + bv.x; o.y = acc[i][1] + bv.y;
            o.z = acc[i][2] + bv.z; o.w = acc[i][3] + bv.w;
            *(float4*)(out + (size_t)node * NF + fg) = o;
        }
    }
}

// ---------------- output head -----------------------------------------------
__global__ void k_gemm3(const float* __restrict__ H, const float* __restrict__ W,
                        float* __restrict__ out) {
    int n = (blockIdx.x * blockDim.x + threadIdx.x) >> 5;
    if (n >= NN) return;
    int lane = threadIdx.x & 31;
    float4 h = *(const float4*)(H + (size_t)n * NF + lane * 4);
    h.x = h.x > 0.f ? h.x : h.x * SLOPE;
    h.y = h.y > 0.f ? h.y : h.y * SLOPE;
    h.z = h.z > 0.f ? h.z : h.z * SLOPE;
    h.w = h.w > 0.f ? h.w : h.w * SLOPE;
    float hv[4] = {h.x, h.y, h.z, h.w};
    float a0 = 0.f, a1 = 0.f, a2 = 0.f;
    #pragma unroll
    for (int j = 0; j < 4; j++) {
        int k = lane * 4 + j;
        a0 += hv[j] * __ldg(W + k * 3 + 0);
        a1 += hv[j] * __ldg(W + k * 3 + 1);
        a2 += hv[j] * __ldg(W + k * 3 + 2);
    }
    #pragma unroll
    for (int o = 16; o > 0; o >>= 1) {
        a0 += __shfl_down_sync(0xffffffffu, a0, o);
        a1 += __shfl_down_sync(0xffffffffu, a1, o);
        a2 += __shfl_down_sync(0xffffffffu, a2, o);
    }
    if (lane == 0) {
        out[n * 3 + 0] = a0;
        out[n * 3 + 1] = a1;
        out[n * 3 + 2] = a2;
    }
}

// ---------------- launch -----------------------------------------------------
extern "C" void kernel_launch(void* const* d_in, const int* in_sizes, int n_in,
                              void* d_out, int out_size) {
    const float* x    = (const float*)d_in[0];
    const void*  ei   = d_in[1];
    const float* W0   = (const float*)d_in[2];
    const float* b0   = (const float*)d_in[3];
    const float* Wh   = (const float*)d_in[4];
    const float* bh   = (const float*)d_in[5];
    const float* Wout = (const float*)d_in[6];
    const float* bout = (const float*)d_in[7];
    float* out = (float*)d_out;

    void *pA, *pB;
    cudaGetSymbolAddress(&pA, g_bufA);
    cudaGetSymbolAddress(&pB, g_bufB);
    float* A = (float*)pA;
    float* B = (float*)pB;

    const int SCAN_SMEM = (NN + 1024) * 4;  // 124 KB
    cudaFuncSetAttribute(k_scan, cudaFuncAttributeMaxDynamicSharedMemorySize, SCAN_SMEM);

    // graph preprocessing
    k_detect<<<1, 32>>>((const unsigned int*)ei);
    k_init_cnt<<<(NN + 255) / 256, 256>>>();
    k_count<<<(EE + 255) / 256, 256>>>(ei);
    k_scan<<<1, 1024, SCAN_SMEM>>>();
    k_fill<<<(EN + 255) / 256, 256>>>(ei);

    const int warpBlocks = (NN * 32 + 255) / 256;   // one warp per node
    const int gemmBlocks = (NN + 31) / 32;

    // layer 0:  h = (A x) @ W0 + b0
    k_agg64<<<warpBlocks, 256>>>(x, A);
    k_gemm<64, false, true><<<gemmBlocks, 256>>>(A, W0, b0, B);

    // 6 hidden layers:  h = A(leaky(h) @ Wh[i]) + bh[i]
    for (int i = 0; i < 6; i++) {
        k_gemm<128, true, false><<<gemmBlocks, 256>>>(B, Wh + (size_t)i * NF * NF, nullptr, A);
        k_agg128<<<warpBlocks, 256>>>(A, bh + (size_t)i * NF, B);
    }

    // output layer: out = tanh(A(leaky(h) @ Wout) + bout) * 0.5
    k_gemm3<<<warpBlocks, 256>>>(B, Wout, A);
    k_agg3<<<warpBlocks, 256>>>(A, bout, out);
}

// round 6
// speedup vs baseline: 1.8866x; 1.4493x over previous
#include <cuda_runtime.h>
#include <cuda_bf16.h>
#include <math.h>
#include <stdint.h>

#define NN 30000
#define EE 480000
#define EN (EE + NN)
#define NF 128
#define SLOPE 0.02f

// ---------------- scratch (device globals; no allocation allowed) ----------
__device__ int   g_cnt[NN];
__device__ float g_dinv[NN];
__device__ int   g_rowptr[NN + 1];
__device__ int   g_fill[NN];
__device__ int   g_csr_src[EN];
__device__ float g_csr_w[EN];
__device__ float g_bufA[NN * NF];
__device__ float g_bufB[NN * NF];
__device__ int   g_is64;
__device__ int   g_bsum[128];
// pre-imaged weights (exact swizzled smem byte layout), bf16 hi/lo planes.
// hidden: 6 layers x (hi 32KB + lo 32KB); layer0: hi 16KB + lo 16KB.
__device__ unsigned short g_wimg_h[6 * 2 * 16384];
__device__ unsigned short g_wimg_0[2 * 8192];

// ---------------- mma/ldmatrix helpers (plain sm_103-safe PTX) -------------
__device__ __forceinline__ uint32_t smem_u32(const void* p) {
    uint32_t a;
    asm("{ .reg .u64 t; cvta.to.shared.u64 t, %1; cvt.u32.u64 %0, t; }"
        : "=r"(a) : "l"(p));
    return a;
}

#define LDSM_X4(r0, r1, r2, r3, addr) \
    asm volatile("ldmatrix.sync.aligned.m8n8.x4.shared.b16 {%0,%1,%2,%3}, [%4];" \
                 : "=r"(r0), "=r"(r1), "=r"(r2), "=r"(r3) : "r"(addr))

#define MMA16816(d, a, b) \
    asm volatile("mma.sync.aligned.m16n8k16.row.col.f32.bf16.bf16.f32 " \
                 "{%0,%1,%2,%3}, {%4,%5,%6,%7}, {%8,%9}, {%0,%1,%2,%3};" \
                 : "+f"((d)[0]), "+f"((d)[1]), "+f"((d)[2]), "+f"((d)[3]) \
                 : "r"((a)[0]), "r"((a)[1]), "r"((a)[2]), "r"((a)[3]), \
                   "r"((b)[0]), "r"((b)[1]))

// pack two fp32 -> bf16x2 word, v0 in low half, v1 in high half
__device__ __forceinline__ uint32_t pack_pair(float v0, float v1) {
    uint32_t r;
    asm("cvt.rn.bf16x2.f32 %0, %1, %2;" : "=r"(r) : "f"(v1), "f"(v0));
    return r;
}

// ---------------- edge-index dtype detection --------------------------------
__global__ void k_detect(const unsigned int* __restrict__ w) {
    int lane = threadIdx.x;
    unsigned bad = 0;
    for (int i = lane; i < 128; i += 32) bad |= w[2 * i + 1];
    #pragma unroll
    for (int o = 16; o > 0; o >>= 1) bad |= __shfl_xor_sync(0xffffffffu, bad, o);
    if (lane == 0) g_is64 = (bad == 0u);
}

__device__ __forceinline__ int edge_at(const void* ei, int idx) {
    return g_is64 ? (int)((const long long*)ei)[idx] : ((const int*)ei)[idx];
}

// ---------------- graph preprocessing ---------------------------------------
__global__ void k_init_cnt() {
    int i = blockIdx.x * blockDim.x + threadIdx.x;
    if (i < NN) g_cnt[i] = 1;
}

__global__ void k_count(const void* __restrict__ ei) {
    int e = blockIdx.x * blockDim.x + threadIdx.x;
    if (e < EE) atomicAdd(&g_cnt[edge_at(ei, EE + e)], 1);
}

// multi-block scan: A) per-block sums  B) scan partials  C) local scan + write
__global__ void k_scanA() {
    int i = blockIdx.x * 256 + threadIdx.x;
    int v = (i < NN) ? g_cnt[i] : 0;
    __shared__ int sh[8];
    #pragma unroll
    for (int o = 16; o > 0; o >>= 1) v += __shfl_down_sync(0xffffffffu, v, o);
    if ((threadIdx.x & 31) == 0) sh[threadIdx.x >> 5] = v;
    __syncthreads();
    if (threadIdx.x < 8) {
        int t = sh[threadIdx.x];
        #pragma unroll
        for (int o = 4; o > 0; o >>= 1) t += __shfl_down_sync(0xffu, t, o);
        if (threadIdx.x == 0) g_bsum[blockIdx.x] = t;
    }
}

__global__ void k_scanB(int nblk) {
    __shared__ int sh[128];
    int t = threadIdx.x;
    int v = (t < nblk) ? g_bsum[t] : 0;
    sh[t] = v;
    __syncthreads();
    #pragma unroll
    for (int d = 1; d < 128; d <<= 1) {
        int a = (t >= d) ? sh[t - d] : 0;
        __syncthreads();
        sh[t] += a;
        __syncthreads();
    }
    if (t < nblk) g_bsum[t] = sh[t] - v;   // exclusive
    if (t == 127) g_rowptr[NN] = sh[127];
}

__global__ void k_scanC() {
    __shared__ int sh[256];
    int tid = threadIdx.x;
    int i = blockIdx.x * 256 + tid;
    int v = (i < NN) ? g_cnt[i] : 0;
    sh[tid] = v;
    __syncthreads();
    #pragma unroll
    for (int d = 1; d < 256; d <<= 1) {
        int a = (tid >= d) ? sh[tid - d] : 0;
        __syncthreads();
        sh[tid] += a;
        __syncthreads();
    }
    if (i < NN) {
        int excl = sh[tid] - v + g_bsum[blockIdx.x];
        g_rowptr[i] = excl;
        g_fill[i]   = excl;
        g_dinv[i]   = rsqrtf((float)v);
    }
}

__global__ void k_fill(const void* __restrict__ ei) {
    int e = blockIdx.x * blockDim.x + threadIdx.x;
    if (e < EE) {
        int s = edge_at(ei, e);
        int d = edge_at(ei, EE + e);
        int pos = atomicAdd(&g_fill[d], 1);
        g_csr_src[pos] = s;
        g_csr_w[pos]   = g_dinv[s] * g_dinv[d];
    } else if (e < EN) {
        int i = e - EE;
        int pos = atomicAdd(&g_fill[i], 1);
        float di = g_dinv[i];
        g_csr_src[pos] = i;
        g_csr_w[pos]   = di * di;
    }
}

// ---------------- weight pre-imaging ----------------------------------------
// B operand layout: [f (=n) rows][k cols] bf16, pitch K*2 bytes, 16B chunks
// swizzled: chunk' = chunk ^ (row & 7). W given as [K][F] row-major.
__global__ void k_prep_wh(const float* __restrict__ Wh) {
    int idx = blockIdx.x * 256 + threadIdx.x;   // 6 layers * 128 f * 16 chunks
    if (idx >= 6 * 128 * 16) return;
    int i = idx / (128 * 16);
    int r = idx % (128 * 16);
    int f = r / 16;
    int chunk = r % 16;
    const float* W = Wh + (size_t)i * 16384;
    float v[8];
    #pragma unroll
    for (int j = 0; j < 8; j++) v[j] = W[(chunk * 8 + j) * 128 + f];
    uint4 hi, lo;
    float h[8];
    #pragma unroll
    for (int j = 0; j < 8; j++) h[j] = __bfloat162float(__float2bfloat16(v[j]));
    hi = make_uint4(pack_pair(h[0], h[1]), pack_pair(h[2], h[3]),
                    pack_pair(h[4], h[5]), pack_pair(h[6], h[7]));
    lo = make_uint4(pack_pair(v[0] - h[0], v[1] - h[1]), pack_pair(v[2] - h[2], v[3] - h[3]),
                    pack_pair(v[4] - h[4], v[5] - h[5]), pack_pair(v[6] - h[6], v[7] - h[7]));
    int off = f * 256 + ((chunk ^ (f & 7)) << 4);
    char* base = (char*)g_wimg_h + (size_t)i * 65536;
    *(uint4*)(base + off)         = hi;
    *(uint4*)(base + 32768 + off) = lo;
}

__global__ void k_prep_w0(const float* __restrict__ W0) {
    int idx = blockIdx.x * 256 + threadIdx.x;   // 128 f * 8 chunks (K=64)
    if (idx >= 128 * 8) return;
    int f = idx / 8;
    int chunk = idx % 8;
    float v[8];
    #pragma unroll
    for (int j = 0; j < 8; j++) v[j] = W0[(chunk * 8 + j) * 128 + f];
    float h[8];
    #pragma unroll
    for (int j = 0; j < 8; j++) h[j] = __bfloat162float(__float2bfloat16(v[j]));
    uint4 hi = make_uint4(pack_pair(h[0], h[1]), pack_pair(h[2], h[3]),
                          pack_pair(h[4], h[5]), pack_pair(h[6], h[7]));
    uint4 lo = make_uint4(pack_pair(v[0] - h[0], v[1] - h[1]), pack_pair(v[2] - h[2], v[3] - h[3]),
                          pack_pair(v[4] - h[4], v[5] - h[5]), pack_pair(v[6] - h[6], v[7] - h[7]));
    int off = f * 128 + ((chunk ^ (f & 7)) << 4);
    char* base = (char*)g_wimg_0;
    *(uint4*)(base + off)         = hi;
    *(uint4*)(base + 16384 + off) = lo;
}

// ---------------- tensor GEMM: 128 nodes x 128 outs per block ---------------
// D = Ah*Bh + Ah*Bl + Al*Bh (bf16 hi/lo split, fp32 accumulate via mma.sync).
template<int K, bool ACT, bool BIAS>
__global__ void __launch_bounds__(256) k_gemm_mma(const float* __restrict__ H,
                                                  const unsigned short* __restrict__ Wimg,
                                                  const float* __restrict__ bias,
                                                  float* __restrict__ out) {
    extern __shared__ char smem[];
    constexpr int PITCH  = K * 2;          // bytes per row
    constexpr int PBYTES = 128 * PITCH;    // one part (A or B plane)
    constexpr int OFF_AH = 0;
    constexpr int OFF_AL = PBYTES;
    constexpr int OFF_BH = 2 * PBYTES;
    constexpr int OFF_BL = 3 * PBYTES;
    const int tid  = threadIdx.x;
    const int wid  = tid >> 5;
    const int lane = tid & 31;
    const int node0 = blockIdx.x * 128;
    const uint32_t sb = smem_u32(smem);

    // copy W image (hi plane then lo plane contiguous): 2*PBYTES bytes
    {
        const uint4* src = (const uint4*)Wimg;
        uint4* dst = (uint4*)(smem + OFF_BH);
        #pragma unroll
        for (int i = tid; i < 2 * PBYTES / 16; i += 256) dst[i] = src[i];
    }
    // stage A: 128 rows x K/8 chunks; activation + hi/lo split + swizzle
    {
        constexpr int NCH = K / 8;
        #pragma unroll
        for (int idx = tid; idx < 128 * NCH; idx += 256) {
            int row = idx / NCH;
            int chunk = idx % NCH;
            int node = node0 + row;
            float4 v0 = make_float4(0.f, 0.f, 0.f, 0.f), v1 = v0;
            if (node < NN) {
                v0 = __ldg((const float4*)(H + (size_t)node * K + chunk * 8));
                v1 = __ldg((const float4*)(H + (size_t)node * K + chunk * 8 + 4));
            }
            float f[8] = {v0.x, v0.y, v0.z, v0.w, v1.x, v1.y, v1.z, v1.w};
            float h[8];
            #pragma unroll
            for (int j = 0; j < 8; j++) {
                float a = f[j];
                if (ACT) a = a > 0.f ? a : a * SLOPE;
                f[j] = a;
                h[j] = __bfloat162float(__float2bfloat16(a));
            }
            uint4 hi = make_uint4(pack_pair(h[0], h[1]), pack_pair(h[2], h[3]),
                                  pack_pair(h[4], h[5]), pack_pair(h[6], h[7]));
            uint4 lo = make_uint4(pack_pair(f[0] - h[0], f[1] - h[1]),
                                  pack_pair(f[2] - h[2], f[3] - h[3]),
                                  pack_pair(f[4] - h[4], f[5] - h[5]),
                                  pack_pair(f[6] - h[6], f[7] - h[7]));
            int off = row * PITCH + ((chunk ^ (row & 7)) << 4);
            *(uint4*)(smem + OFF_AH + off) = hi;
            *(uint4*)(smem + OFF_AL + off) = lo;
        }
    }
    __syncthreads();

    // warp tile: 4x2 warp grid; warp computes 32 rows x 64 cols
    const int mrow0 = (wid & 3) * 32;
    const int ncol0 = (wid >> 2) * 64;
    float acc[2][8][4] = {};

    // three split products: (Ah,Bh), (Ah,Bl), (Al,Bh)
    const uint32_t aOff[3] = {sb + OFF_AH, sb + OFF_AH, sb + OFF_AL};
    const uint32_t bOff[3] = {sb + OFF_BH, sb + OFF_BL, sb + OFF_BH};

    #pragma unroll
    for (int t = 0; t < 3; t++) {
        const uint32_t aB = aOff[t], bB = bOff[t];
        #pragma unroll
        for (int ks = 0; ks < K / 16; ks++) {
            uint32_t a[2][4], b[8][2];
            #pragma unroll
            for (int i = 0; i < 2; i++) {
                int row = mrow0 + i * 16 + (lane & 15);
                int chunk = ks * 2 + (lane >> 4);
                uint32_t addr = aB + row * PITCH + ((chunk ^ (row & 7)) << 4);
                LDSM_X4(a[i][0], a[i][1], a[i][2], a[i][3], addr);
            }
            #pragma unroll
            for (int p = 0; p < 4; p++) {
                int nrow = ncol0 + p * 16 + (lane >> 4) * 8 + (lane & 7);
                int chunk = ks * 2 + ((lane >> 3) & 1);
                uint32_t addr = bB + nrow * PITCH + ((chunk ^ (nrow & 7)) << 4);
                LDSM_X4(b[2 * p][0], b[2 * p][1], b[2 * p + 1][0], b[2 * p + 1][1], addr);
            }
            #pragma unroll
            for (int i = 0; i < 2; i++)
                #pragma unroll
                for (int j = 0; j < 8; j++)
                    MMA16816(acc[i][j], a[i], b[j]);
        }
    }

    // epilogue
    #pragma unroll
    for (int i = 0; i < 2; i++) {
        #pragma unroll
        for (int j = 0; j < 8; j++) {
            int c = ncol0 + j * 8 + (lane & 3) * 2;
            float2 bb = make_float2(0.f, 0.f);
            if (BIAS) bb = *(const float2*)(bias + c);
            int r0 = node0 + mrow0 + i * 16 + (lane >> 2);
            if (r0 < NN)
                *(float2*)(out + (size_t)r0 * NF + c) =
                    make_float2(acc[i][j][0] + bb.x, acc[i][j][1] + bb.y);
            int r1 = r0 + 8;
            if (r1 < NN)
                *(float2*)(out + (size_t)r1 * NF + c) =
                    make_float2(acc[i][j][2] + bb.x, acc[i][j][3] + bb.y);
        }
    }
}

// ---------------- aggregation kernels (one warp per node, proven) -----------
__global__ void k_agg64(const float* __restrict__ X, float* __restrict__ out) {
    int n = (blockIdx.x * blockDim.x + threadIdx.x) >> 5;
    if (n >= NN) return;
    int lane = threadIdx.x & 31;
    int beg = g_rowptr[n], end = g_rowptr[n + 1];
    float2 acc = make_float2(0.f, 0.f);
    int j = beg;
    for (; j + 3 < end; j += 4) {
        int   s0 = g_csr_src[j],   s1 = g_csr_src[j+1],
              s2 = g_csr_src[j+2], s3 = g_csr_src[j+3];
        float w0 = g_csr_w[j],   w1 = g_csr_w[j+1],
              w2 = g_csr_w[j+2], w3 = g_csr_w[j+3];
        float2 v0 = __ldg((const float2*)(X + s0 * 64 + lane * 2));
        float2 v1 = __ldg((const float2*)(X + s1 * 64 + lane * 2));
        float2 v2 = __ldg((const float2*)(X + s2 * 64 + lane * 2));
        float2 v3 = __ldg((const float2*)(X + s3 * 64 + lane * 2));
        acc.x += w0*v0.x + w1*v1.x + w2*v2.x + w3*v3.x;
        acc.y += w0*v0.y + w1*v1.y + w2*v2.y + w3*v3.y;
    }
    for (; j < end; j++) {
        int s = g_csr_src[j]; float w = g_csr_w[j];
        float2 v = __ldg((const float2*)(X + s * 64 + lane * 2));
        acc.x += w * v.x; acc.y += w * v.y;
    }
    *(float2*)(out + n * 64 + lane * 2) = acc;
}

__global__ void k_agg128(const float* __restrict__ T, const float* __restrict__ bias,
                         float* __restrict__ out) {
    int n = (blockIdx.x * blockDim.x + threadIdx.x) >> 5;
    if (n >= NN) return;
    int lane = threadIdx.x & 31;
    int beg = g_rowptr[n], end = g_rowptr[n + 1];
    float4 acc = make_float4(0.f, 0.f, 0.f, 0.f);
    int j = beg;
    for (; j + 3 < end; j += 4) {
        int   s0 = g_csr_src[j],   s1 = g_csr_src[j+1],
              s2 = g_csr_src[j+2], s3 = g_csr_src[j+3];
        float w0 = g_csr_w[j],   w1 = g_csr_w[j+1],
              w2 = g_csr_w[j+2], w3 = g_csr_w[j+3];
        float4 v0 = __ldg((const float4*)(T + s0 * NF + lane * 4));
        float4 v1 = __ldg((const float4*)(T + s1 * NF + lane * 4));
        float4 v2 = __ldg((const float4*)(T + s2 * NF + lane * 4));
        float4 v3 = __ldg((const float4*)(T + s3 * NF + lane * 4));
        acc.x += w0*v0.x + w1*v1.x + w2*v2.x + w3*v3.x;
        acc.y += w0*v0.y + w1*v1.y + w2*v2.y + w3*v3.y;
        acc.z += w0*v0.z + w1*v1.z + w2*v2.z + w3*v3.z;
        acc.w += w0*v0.w + w1*v1.w + w2*v2.w + w3*v3.w;
    }
    for (; j < end; j++) {
        int s = g_csr_src[j]; float w = g_csr_w[j];
        float4 v = __ldg((const float4*)(T + s * NF + lane * 4));
        acc.x += w*v.x; acc.y += w*v.y; acc.z += w*v.z; acc.w += w*v.w;
    }
    float4 b = __ldg((const float4*)(bias + lane * 4));
    acc.x += b.x; acc.y += b.y; acc.z += b.z; acc.w += b.w;
    *(float4*)(out + n * NF + lane * 4) = acc;
}

__global__ void k_agg3(const float* __restrict__ T, const float* __restrict__ bout,
                       float* __restrict__ out) {
    int n = (blockIdx.x * blockDim.x + threadIdx.x) >> 5;
    if (n >= NN) return;
    int lane = threadIdx.x & 31;
    int beg = g_rowptr[n], end = g_rowptr[n + 1];
    float a0 = 0.f, a1 = 0.f, a2 = 0.f;
    for (int j = beg + lane; j < end; j += 32) {
        int s = g_csr_src[j]; float w = g_csr_w[j];
        a0 += w * __ldg(T + s * 3 + 0);
        a1 += w * __ldg(T + s * 3 + 1);
        a2 += w * __ldg(T + s * 3 + 2);
    }
    #pragma unroll
    for (int o = 16; o > 0; o >>= 1) {
        a0 += __shfl_down_sync(0xffffffffu, a0, o);
        a1 += __shfl_down_sync(0xffffffffu, a1, o);
        a2 += __shfl_down_sync(0xffffffffu, a2, o);
    }
    if (lane == 0) {
        out[n * 3 + 0] = tanhf(a0 + __ldg(bout + 0)) * 0.5f;
        out[n * 3 + 1] = tanhf(a1 + __ldg(bout + 1)) * 0.5f;
        out[n * 3 + 2] = tanhf(a2 + __ldg(bout + 2)) * 0.5f;
    }
}

// ---------------- output head -----------------------------------------------
__global__ void k_gemm3(const float* __restrict__ H, const float* __restrict__ W,
                        float* __restrict__ out) {
    int n = (blockIdx.x * blockDim.x + threadIdx.x) >> 5;
    if (n >= NN) return;
    int lane = threadIdx.x & 31;
    float4 h = *(const float4*)(H + (size_t)n * NF + lane * 4);
    h.x = h.x > 0.f ? h.x : h.x * SLOPE;
    h.y = h.y > 0.f ? h.y : h.y * SLOPE;
    h.z = h.z > 0.f ? h.z : h.z * SLOPE;
    h.w = h.w > 0.f ? h.w : h.w * SLOPE;
    float hv[4] = {h.x, h.y, h.z, h.w};
    float a0 = 0.f, a1 = 0.f, a2 = 0.f;
    #pragma unroll
    for (int j = 0; j < 4; j++) {
        int k = lane * 4 + j;
        a0 += hv[j] * __ldg(W + k * 3 + 0);
        a1 += hv[j] * __ldg(W + k * 3 + 1);
        a2 += hv[j] * __ldg(W + k * 3 + 2);
    }
    #pragma unroll
    for (int o = 16; o > 0; o >>= 1) {
        a0 += __shfl_down_sync(0xffffffffu, a0, o);
        a1 += __shfl_down_sync(0xffffffffu, a1, o);
        a2 += __shfl_down_sync(0xffffffffu, a2, o);
    }
    if (lane == 0) {
        out[n * 3 + 0] = a0;
        out[n * 3 + 1] = a1;
        out[n * 3 + 2] = a2;
    }
}

// ---------------- launch -----------------------------------------------------
extern "C" void kernel_launch(void* const* d_in, const int* in_sizes, int n_in,
                              void* d_out, int out_size) {
    const float* x    = (const float*)d_in[0];
    const void*  ei   = d_in[1];
    const float* W0   = (const float*)d_in[2];
    const float* b0   = (const float*)d_in[3];
    const float* Wh   = (const float*)d_in[4];
    const float* bh   = (const float*)d_in[5];
    const float* Wout = (const float*)d_in[6];
    const float* bout = (const float*)d_in[7];
    float* out = (float*)d_out;

    void *pA, *pB, *pWh, *pW0;
    cudaGetSymbolAddress(&pA, g_bufA);
    cudaGetSymbolAddress(&pB, g_bufB);
    cudaGetSymbolAddress(&pWh, g_wimg_h);
    cudaGetSymbolAddress(&pW0, g_wimg_0);
    float* A = (float*)pA;
    float* B = (float*)pB;
    const unsigned short* WIH = (const unsigned short*)pWh;
    const unsigned short* WI0 = (const unsigned short*)pW0;

    const int SM128 = 4 * 128 * 128 * 2;  // 128 KB
    const int SM64  = 4 * 128 * 64 * 2;   //  64 KB
    cudaFuncSetAttribute(k_gemm_mma<128, true, false>,
                         cudaFuncAttributeMaxDynamicSharedMemorySize, SM128);
    cudaFuncSetAttribute(k_gemm_mma<64, false, true>,
                         cudaFuncAttributeMaxDynamicSharedMemorySize, SM64);

    const int scanBlocks = (NN + 255) / 256;  // 118

    // graph preprocessing
    k_detect<<<1, 32>>>((const unsigned int*)ei);
    k_init_cnt<<<scanBlocks, 256>>>();
    k_count<<<(EE + 255) / 256, 256>>>(ei);
    k_scanA<<<scanBlocks, 256>>>();
    k_scanB<<<1, 128>>>(scanBlocks);
    k_scanC<<<scanBlocks, 256>>>();
    k_fill<<<(EN + 255) / 256, 256>>>(ei);

    // weight images
    k_prep_wh<<<(6 * 128 * 16 + 255) / 256, 256>>>(Wh);
    k_prep_w0<<<(128 * 8 + 255) / 256, 256>>>(W0);

    const int warpBlocks = (NN * 32 + 255) / 256;   // one warp per node
    const int tcBlocks   = (NN + 127) / 128;        // 235

    // layer 0:  B = (A x) @ W0 + b0
    k_agg64<<<warpBlocks, 256>>>(x, A);
    k_gemm_mma<64, false, true><<<tcBlocks, 256, SM64>>>(A, WI0, b0, B);

    // 6 hidden layers:  h = A(leaky(h) @ Wh[i]) + bh[i]
    for (int i = 0; i < 6; i++) {
        k_gemm_mma<128, true, false><<<tcBlocks, 256, SM128>>>(
            B, WIH + (size_t)i * 32768, nullptr, A);
        k_agg128<<<warpBlocks, 256>>>(A, bh + (size_t)i * NF, B);
    }

    // output: out = tanh( A (leaky(h) @ Wout) + bout ) * 0.5
    k_gemm3<<<warpBlocks, 256>>>(B, Wout, A);
    k_agg3<<<warpBlocks, 256>>>(A, bout, out);
}

// round 7
// speedup vs baseline: 2.0817x; 1.1034x over previous
#include <cuda_runtime.h>
#include <cuda_bf16.h>
#include <cuda_fp16.h>
#include <math.h>
#include <stdint.h>

#define NN 30000
#define EE 480000
#define EN (EE + NN)
#define NF 128
#define SLOPE 0.02f

// ---------------- scratch (device globals; no allocation allowed) ----------
__device__ int   g_cnt[NN];
__device__ float g_dinv[NN];
__device__ int   g_rowptr[NN + 1];
__device__ int   g_fill[NN];
__device__ int   g_csr_src[EN];
__device__ float g_csr_w[EN];
__device__ float g_bufA[NN * NF];
__device__ float g_bufB[NN * NF];
__device__ __half g_bufM[NN * NF];   // fp16 message buffer (gathered operand)
__device__ __half g_x16[NN * 64];    // fp16 copy of input x
__device__ int   g_is64;
__device__ int   g_bsum[128];
// pre-imaged weights (exact swizzled smem byte layout), bf16 hi/lo planes.
__device__ unsigned short g_wimg_h[6 * 2 * 16384];
__device__ unsigned short g_wimg_0[2 * 8192];

// ---------------- mma/ldmatrix helpers (plain sm_103-safe PTX) -------------
__device__ __forceinline__ uint32_t smem_u32(const void* p) {
    uint32_t a;
    asm("{ .reg .u64 t; cvta.to.shared.u64 t, %1; cvt.u32.u64 %0, t; }"
        : "=r"(a) : "l"(p));
    return a;
}

#define LDSM_X4(r0, r1, r2, r3, addr) \
    asm volatile("ldmatrix.sync.aligned.m8n8.x4.shared.b16 {%0,%1,%2,%3}, [%4];" \
                 : "=r"(r0), "=r"(r1), "=r"(r2), "=r"(r3) : "r"(addr))

#define MMA16816(d, a, b) \
    asm volatile("mma.sync.aligned.m16n8k16.row.col.f32.bf16.bf16.f32 " \
                 "{%0,%1,%2,%3}, {%4,%5,%6,%7}, {%8,%9}, {%0,%1,%2,%3};" \
                 : "+f"((d)[0]), "+f"((d)[1]), "+f"((d)[2]), "+f"((d)[3]) \
                 : "r"((a)[0]), "r"((a)[1]), "r"((a)[2]), "r"((a)[3]), \
                   "r"((b)[0]), "r"((b)[1]))

__device__ __forceinline__ uint32_t pack_pair(float v0, float v1) {
    uint32_t r;
    asm("cvt.rn.bf16x2.f32 %0, %1, %2;" : "=r"(r) : "f"(v1), "f"(v0));
    return r;
}

// ---------------- edge-index dtype detection --------------------------------
__global__ void k_detect(const unsigned int* __restrict__ w) {
    int lane = threadIdx.x;
    unsigned bad = 0;
    for (int i = lane; i < 128; i += 32) bad |= w[2 * i + 1];
    #pragma unroll
    for (int o = 16; o > 0; o >>= 1) bad |= __shfl_xor_sync(0xffffffffu, bad, o);
    if (lane == 0) g_is64 = (bad == 0u);
}

__device__ __forceinline__ int edge_at(const void* ei, int idx) {
    return g_is64 ? (int)((const long long*)ei)[idx] : ((const int*)ei)[idx];
}

// ---------------- graph preprocessing ---------------------------------------
__global__ void k_init_cnt() {
    int i = blockIdx.x * blockDim.x + threadIdx.x;
    if (i < NN) g_cnt[i] = 1;
}

__global__ void k_count(const void* __restrict__ ei) {
    int e = blockIdx.x * blockDim.x + threadIdx.x;
    if (e < EE) atomicAdd(&g_cnt[edge_at(ei, EE + e)], 1);
}

__global__ void k_scanA() {
    int i = blockIdx.x * 256 + threadIdx.x;
    int v = (i < NN) ? g_cnt[i] : 0;
    __shared__ int sh[8];
    #pragma unroll
    for (int o = 16; o > 0; o >>= 1) v += __shfl_down_sync(0xffffffffu, v, o);
    if ((threadIdx.x & 31) == 0) sh[threadIdx.x >> 5] = v;
    __syncthreads();
    if (threadIdx.x < 8) {
        int t = sh[threadIdx.x];
        #pragma unroll
        for (int o = 4; o > 0; o >>= 1) t += __shfl_down_sync(0xffu, t, o);
        if (threadIdx.x == 0) g_bsum[blockIdx.x] = t;
    }
}

__global__ void k_scanB(int nblk) {
    __shared__ int sh[128];
    int t = threadIdx.x;
    int v = (t < nblk) ? g_bsum[t] : 0;
    sh[t] = v;
    __syncthreads();
    #pragma unroll
    for (int d = 1; d < 128; d <<= 1) {
        int a = (t >= d) ? sh[t - d] : 0;
        __syncthreads();
        sh[t] += a;
        __syncthreads();
    }
    if (t < nblk) g_bsum[t] = sh[t] - v;
    if (t == 127) g_rowptr[NN] = sh[127];
}

__global__ void k_scanC() {
    __shared__ int sh[256];
    int tid = threadIdx.x;
    int i = blockIdx.x * 256 + tid;
    int v = (i < NN) ? g_cnt[i] : 0;
    sh[tid] = v;
    __syncthreads();
    #pragma unroll
    for (int d = 1; d < 256; d <<= 1) {
        int a = (tid >= d) ? sh[tid - d] : 0;
        __syncthreads();
        sh[tid] += a;
        __syncthreads();
    }
    if (i < NN) {
        int excl = sh[tid] - v + g_bsum[blockIdx.x];
        g_rowptr[i] = excl;
        g_fill[i]   = excl;
        g_dinv[i]   = rsqrtf((float)v);
    }
}

__global__ void k_fill(const void* __restrict__ ei) {
    int e = blockIdx.x * blockDim.x + threadIdx.x;
    if (e < EE) {
        int s = edge_at(ei, e);
        int d = edge_at(ei, EE + e);
        int pos = atomicAdd(&g_fill[d], 1);
        g_csr_src[pos] = s;
        g_csr_w[pos]   = g_dinv[s] * g_dinv[d];
    } else if (e < EN) {
        int i = e - EE;
        int pos = atomicAdd(&g_fill[i], 1);
        float di = g_dinv[i];
        g_csr_src[pos] = i;
        g_csr_w[pos]   = di * di;
    }
}

// convert x to fp16 (once per replay)
__global__ void k_x16(const float* __restrict__ x) {
    int i = blockIdx.x * 256 + threadIdx.x;   // over NN*32 half2
    if (i < NN * 32) {
        float2 v = __ldg((const float2*)(x + 2 * i));
        ((__half2*)g_x16)[i] = __floats2half2_rn(v.x, v.y);
    }
}

// ---------------- weight pre-imaging ----------------------------------------
__global__ void k_prep_wh(const float* __restrict__ Wh) {
    int idx = blockIdx.x * 256 + threadIdx.x;   // 6 layers * 128 f * 16 chunks
    if (idx >= 6 * 128 * 16) return;
    int i = idx / (128 * 16);
    int r = idx % (128 * 16);
    int f = r / 16;
    int chunk = r % 16;
    const float* W = Wh + (size_t)i * 16384;
    float v[8];
    #pragma unroll
    for (int j = 0; j < 8; j++) v[j] = W[(chunk * 8 + j) * 128 + f];
    float h[8];
    #pragma unroll
    for (int j = 0; j < 8; j++) h[j] = __bfloat162float(__float2bfloat16(v[j]));
    uint4 hi = make_uint4(pack_pair(h[0], h[1]), pack_pair(h[2], h[3]),
                          pack_pair(h[4], h[5]), pack_pair(h[6], h[7]));
    uint4 lo = make_uint4(pack_pair(v[0] - h[0], v[1] - h[1]), pack_pair(v[2] - h[2], v[3] - h[3]),
                          pack_pair(v[4] - h[4], v[5] - h[5]), pack_pair(v[6] - h[6], v[7] - h[7]));
    int off = f * 256 + ((chunk ^ (f & 7)) << 4);
    char* base = (char*)g_wimg_h + (size_t)i * 65536;
    *(uint4*)(base + off)         = hi;
    *(uint4*)(base + 32768 + off) = lo;
}

__global__ void k_prep_w0(const float* __restrict__ W0) {
    int idx = blockIdx.x * 256 + threadIdx.x;   // 128 f * 8 chunks (K=64)
    if (idx >= 128 * 8) return;
    int f = idx / 8;
    int chunk = idx % 8;
    float v[8];
    #pragma unroll
    for (int j = 0; j < 8; j++) v[j] = W0[(chunk * 8 + j) * 128 + f];
    float h[8];
    #pragma unroll
    for (int j = 0; j < 8; j++) h[j] = __bfloat162float(__float2bfloat16(v[j]));
    uint4 hi = make_uint4(pack_pair(h[0], h[1]), pack_pair(h[2], h[3]),
                          pack_pair(h[4], h[5]), pack_pair(h[6], h[7]));
    uint4 lo = make_uint4(pack_pair(v[0] - h[0], v[1] - h[1]), pack_pair(v[2] - h[2], v[3] - h[3]),
                          pack_pair(v[4] - h[4], v[5] - h[5]), pack_pair(v[6] - h[6], v[7] - h[7]));
    int off = f * 128 + ((chunk ^ (f & 7)) << 4);
    char* base = (char*)g_wimg_0;
    *(uint4*)(base + off)         = hi;
    *(uint4*)(base + 16384 + off) = lo;
}

// ---------------- tensor GEMM: 128 nodes x 128 outs per block ---------------
// D = Ah*Bh + Ah*Bl + Al*Bh; optional fp16 output (message buffer).
template<int K, bool ACT, bool BIAS, bool OUT16>
__global__ void __launch_bounds__(256) k_gemm_mma(const float* __restrict__ H,
                                                  const unsigned short* __restrict__ Wimg,
                                                  const float* __restrict__ bias,
                                                  void* __restrict__ outv) {
    extern __shared__ char smem[];
    constexpr int PITCH  = K * 2;
    constexpr int PBYTES = 128 * PITCH;
    constexpr int OFF_AH = 0;
    constexpr int OFF_AL = PBYTES;
    constexpr int OFF_BH = 2 * PBYTES;
    constexpr int OFF_BL = 3 * PBYTES;
    const int tid  = threadIdx.x;
    const int wid  = tid >> 5;
    const int lane = tid & 31;
    const int node0 = blockIdx.x * 128;
    const uint32_t sb = smem_u32(smem);

    {
        const uint4* src = (const uint4*)Wimg;
        uint4* dst = (uint4*)(smem + OFF_BH);
        #pragma unroll
        for (int i = tid; i < 2 * PBYTES / 16; i += 256) dst[i] = src[i];
    }
    {
        constexpr int NCH = K / 8;
        #pragma unroll
        for (int idx = tid; idx < 128 * NCH; idx += 256) {
            int row = idx / NCH;
            int chunk = idx % NCH;
            int node = node0 + row;
            float4 v0 = make_float4(0.f, 0.f, 0.f, 0.f), v1 = v0;
            if (node < NN) {
                v0 = __ldg((const float4*)(H + (size_t)node * K + chunk * 8));
                v1 = __ldg((const float4*)(H + (size_t)node * K + chunk * 8 + 4));
            }
            float f[8] = {v0.x, v0.y, v0.z, v0.w, v1.x, v1.y, v1.z, v1.w};
            float h[8];
            #pragma unroll
            for (int j = 0; j < 8; j++) {
                float a = f[j];
                if (ACT) a = a > 0.f ? a : a * SLOPE;
                f[j] = a;
                h[j] = __bfloat162float(__float2bfloat16(a));
            }
            uint4 hi = make_uint4(pack_pair(h[0], h[1]), pack_pair(h[2], h[3]),
                                  pack_pair(h[4], h[5]), pack_pair(h[6], h[7]));
            uint4 lo = make_uint4(pack_pair(f[0] - h[0], f[1] - h[1]),
                                  pack_pair(f[2] - h[2], f[3] - h[3]),
                                  pack_pair(f[4] - h[4], f[5] - h[5]),
                                  pack_pair(f[6] - h[6], f[7] - h[7]));
            int off = row * PITCH + ((chunk ^ (row & 7)) << 4);
            *(uint4*)(smem + OFF_AH + off) = hi;
            *(uint4*)(smem + OFF_AL + off) = lo;
        }
    }
    __syncthreads();

    const int mrow0 = (wid & 3) * 32;
    const int ncol0 = (wid >> 2) * 64;
    float acc[2][8][4] = {};

    const uint32_t aOff[3] = {sb + OFF_AH, sb + OFF_AH, sb + OFF_AL};
    const uint32_t bOff[3] = {sb + OFF_BH, sb + OFF_BL, sb + OFF_BH};

    #pragma unroll
    for (int t = 0; t < 3; t++) {
        const uint32_t aB = aOff[t], bB = bOff[t];
        #pragma unroll
        for (int ks = 0; ks < K / 16; ks++) {
            uint32_t a[2][4], b[8][2];
            #pragma unroll
            for (int i = 0; i < 2; i++) {
                int row = mrow0 + i * 16 + (lane & 15);
                int chunk = ks * 2 + (lane >> 4);
                uint32_t addr = aB + row * PITCH + ((chunk ^ (row & 7)) << 4);
                LDSM_X4(a[i][0], a[i][1], a[i][2], a[i][3], addr);
            }
            #pragma unroll
            for (int p = 0; p < 4; p++) {
                int nrow = ncol0 + p * 16 + (lane >> 4) * 8 + (lane & 7);
                int chunk = ks * 2 + ((lane >> 3) & 1);
                uint32_t addr = bB + nrow * PITCH + ((chunk ^ (nrow & 7)) << 4);
                LDSM_X4(b[2 * p][0], b[2 * p][1], b[2 * p + 1][0], b[2 * p + 1][1], addr);
            }
            #pragma unroll
            for (int i = 0; i < 2; i++)
                #pragma unroll
                for (int j = 0; j < 8; j++)
                    MMA16816(acc[i][j], a[i], b[j]);
        }
    }

    #pragma unroll
    for (int i = 0; i < 2; i++) {
        #pragma unroll
        for (int j = 0; j < 8; j++) {
            int c = ncol0 + j * 8 + (lane & 3) * 2;
            float2 bb = make_float2(0.f, 0.f);
            if (BIAS) bb = *(const float2*)(bias + c);
            int r0 = node0 + mrow0 + i * 16 + (lane >> 2);
            int r1 = r0 + 8;
            if (OUT16) {
                __half* o = (__half*)outv;
                if (r0 < NN)
                    *(__half2*)(o + (size_t)r0 * NF + c) =
                        __floats2half2_rn(acc[i][j][0] + bb.x, acc[i][j][1] + bb.y);
                if (r1 < NN)
                    *(__half2*)(o + (size_t)r1 * NF + c) =
                        __floats2half2_rn(acc[i][j][2] + bb.x, acc[i][j][3] + bb.y);
            } else {
                float* o = (float*)outv;
                if (r0 < NN)
                    *(float2*)(o + (size_t)r0 * NF + c) =
                        make_float2(acc[i][j][0] + bb.x, acc[i][j][1] + bb.y);
                if (r1 < NN)
                    *(float2*)(o + (size_t)r1 * NF + c) =
                        make_float2(acc[i][j][2] + bb.x, acc[i][j][3] + bb.y);
            }
        }
    }
}

// ---------------- aggregation kernels (one warp per node) -------------------
// 64-dim fp16 gather: lane covers 2 features (half2 at index lane)
__global__ void k_agg64(float* __restrict__ out) {
    int n = (blockIdx.x * blockDim.x + threadIdx.x) >> 5;
    if (n >= NN) return;
    int lane = threadIdx.x & 31;
    int beg = g_rowptr[n], end = g_rowptr[n + 1];
    const __half2* X = (const __half2*)g_x16;
    float2 acc = make_float2(0.f, 0.f);
    int j = beg;
    for (; j + 3 < end; j += 4) {
        int   s0 = g_csr_src[j],   s1 = g_csr_src[j+1],
              s2 = g_csr_src[j+2], s3 = g_csr_src[j+3];
        float w0 = g_csr_w[j],   w1 = g_csr_w[j+1],
              w2 = g_csr_w[j+2], w3 = g_csr_w[j+3];
        float2 v0 = __half22float2(__ldg(X + s0 * 32 + lane));
        float2 v1 = __half22float2(__ldg(X + s1 * 32 + lane));
        float2 v2 = __half22float2(__ldg(X + s2 * 32 + lane));
        float2 v3 = __half22float2(__ldg(X + s3 * 32 + lane));
        acc.x += w0*v0.x + w1*v1.x + w2*v2.x + w3*v3.x;
        acc.y += w0*v0.y + w1*v1.y + w2*v2.y + w3*v3.y;
    }
    for (; j < end; j++) {
        int s = g_csr_src[j]; float w = g_csr_w[j];
        float2 v = __half22float2(__ldg(X + s * 32 + lane));
        acc.x += w * v.x; acc.y += w * v.y;
    }
    *(float2*)(out + n * 64 + lane * 2) = acc;
}

// 128-dim fp16 gather: lane covers 4 features (two half2 = uint2 load)
__global__ void k_agg128(const __half* __restrict__ T, const float* __restrict__ bias,
                         float* __restrict__ out) {
    int n = (blockIdx.x * blockDim.x + threadIdx.x) >> 5;
    if (n >= NN) return;
    int lane = threadIdx.x & 31;
    int beg = g_rowptr[n], end = g_rowptr[n + 1];
    float4 acc = make_float4(0.f, 0.f, 0.f, 0.f);
    int j = beg;
    for (; j + 3 < end; j += 4) {
        int   s0 = g_csr_src[j],   s1 = g_csr_src[j+1],
              s2 = g_csr_src[j+2], s3 = g_csr_src[j+3];
        float w0 = g_csr_w[j],   w1 = g_csr_w[j+1],
              w2 = g_csr_w[j+2], w3 = g_csr_w[j+3];
        __half2 p0a = __ldg((const __half2*)(T + s0 * NF + lane * 4));
        __half2 p0b = __ldg((const __half2*)(T + s0 * NF + lane * 4 + 2));
        __half2 p1a = __ldg((const __half2*)(T + s1 * NF + lane * 4));
        __half2 p1b = __ldg((const __half2*)(T + s1 * NF + lane * 4 + 2));
        __half2 p2a = __ldg((const __half2*)(T + s2 * NF + lane * 4));
        __half2 p2b = __ldg((const __half2*)(T + s2 * NF + lane * 4 + 2));
        __half2 p3a = __ldg((const __half2*)(T + s3 * NF + lane * 4));
        __half2 p3b = __ldg((const __half2*)(T + s3 * NF + lane * 4 + 2));
        float2 a0 = __half22float2(p0a), b0 = __half22float2(p0b);
        float2 a1 = __half22float2(p1a), b1 = __half22float2(p1b);
        float2 a2 = __half22float2(p2a), b2 = __half22float2(p2b);
        float2 a3 = __half22float2(p3a), b3 = __half22float2(p3b);
        acc.x += w0*a0.x + w1*a1.x + w2*a2.x + w3*a3.x;
        acc.y += w0*a0.y + w1*a1.y + w2*a2.y + w3*a3.y;
        acc.z += w0*b0.x + w1*b1.x + w2*b2.x + w3*b3.x;
        acc.w += w0*b0.y + w1*b1.y + w2*b2.y + w3*b3.y;
    }
    for (; j < end; j++) {
        int s = g_csr_src[j]; float w = g_csr_w[j];
        float2 a = __half22float2(__ldg((const __half2*)(T + s * NF + lane * 4)));
        float2 b = __half22float2(__ldg((const __half2*)(T + s * NF + lane * 4 + 2)));
        acc.x += w*a.x; acc.y += w*a.y; acc.z += w*b.x; acc.w += w*b.y;
    }
    float4 bb = __ldg((const float4*)(bias + lane * 4));
    acc.x += bb.x; acc.y += bb.y; acc.z += bb.z; acc.w += bb.w;
    *(float4*)(out + n * NF + lane * 4) = acc;
}

__global__ void k_agg3(const float* __restrict__ T, const float* __restrict__ bout,
                       float* __restrict__ out) {
    int n = (blockIdx.x * blockDim.x + threadIdx.x) >> 5;
    if (n >= NN) return;
    int lane = threadIdx.x & 31;
    int beg = g_rowptr[n], end = g_rowptr[n + 1];
    float a0 = 0.f, a1 = 0.f, a2 = 0.f;
    for (int j = beg + lane; j < end; j += 32) {
        int s = g_csr_src[j]; float w = g_csr_w[j];
        a0 += w * __ldg(T + s * 3 + 0);
        a1 += w * __ldg(T + s * 3 + 1);
        a2 += w * __ldg(T + s * 3 + 2);
    }
    #pragma unroll
    for (int o = 16; o > 0; o >>= 1) {
        a0 += __shfl_down_sync(0xffffffffu, a0, o);
        a1 += __shfl_down_sync(0xffffffffu, a1, o);
        a2 += __shfl_down_sync(0xffffffffu, a2, o);
    }
    if (lane == 0) {
        out[n * 3 + 0] = tanhf(a0 + __ldg(bout + 0)) * 0.5f;
        out[n * 3 + 1] = tanhf(a1 + __ldg(bout + 1)) * 0.5f;
        out[n * 3 + 2] = tanhf(a2 + __ldg(bout + 2)) * 0.5f;
    }
}

// ---------------- output head -----------------------------------------------
__global__ void k_gemm3(const float* __restrict__ H, const float* __restrict__ W,
                        float* __restrict__ out) {
    int n = (blockIdx.x * blockDim.x + threadIdx.x) >> 5;
    if (n >= NN) return;
    int lane = threadIdx.x & 31;
    float4 h = *(const float4*)(H + (size_t)n * NF + lane * 4);
    h.x = h.x > 0.f ? h.x : h.x * SLOPE;
    h.y = h.y > 0.f ? h.y : h.y * SLOPE;
    h.z = h.z > 0.f ? h.z : h.z * SLOPE;
    h.w = h.w > 0.f ? h.w : h.w * SLOPE;
    float hv[4] = {h.x, h.y, h.z, h.w};
    float a0 = 0.f, a1 = 0.f, a2 = 0.f;
    #pragma unroll
    for (int j = 0; j < 4; j++) {
        int k = lane * 4 + j;
        a0 += hv[j] * __ldg(W + k * 3 + 0);
        a1 += hv[j] * __ldg(W + k * 3 + 1);
        a2 += hv[j] * __ldg(W + k * 3 + 2);
    }
    #pragma unroll
    for (int o = 16; o > 0; o >>= 1) {
        a0 += __shfl_down_sync(0xffffffffu, a0, o);
        a1 += __shfl_down_sync(0xffffffffu, a1, o);
        a2 += __shfl_down_sync(0xffffffffu, a2, o);
    }
    if (lane == 0) {
        out[n * 3 + 0] = a0;
        out[n * 3 + 1] = a1;
        out[n * 3 + 2] = a2;
    }
}

// ---------------- launch -----------------------------------------------------
extern "C" void kernel_launch(void* const* d_in, const int* in_sizes, int n_in,
                              void* d_out, int out_size) {
    const float* x    = (const float*)d_in[0];
    const void*  ei   = d_in[1];
    const float* W0   = (const float*)d_in[2];
    const float* b0   = (const float*)d_in[3];
    const float* Wh   = (const float*)d_in[4];
    const float* bh   = (const float*)d_in[5];
    const float* Wout = (const float*)d_in[6];
    const float* bout = (const float*)d_in[7];
    float* out = (float*)d_out;

    void *pA, *pB, *pM, *pWh, *pW0;
    cudaGetSymbolAddress(&pA, g_bufA);
    cudaGetSymbolAddress(&pB, g_bufB);
    cudaGetSymbolAddress(&pM, g_bufM);
    cudaGetSymbolAddress(&pWh, g_wimg_h);
    cudaGetSymbolAddress(&pW0, g_wimg_0);
    float* A = (float*)pA;
    float* B = (float*)pB;
    __half* M16 = (__half*)pM;
    const unsigned short* WIH = (const unsigned short*)pWh;
    const unsigned short* WI0 = (const unsigned short*)pW0;

    const int SM128 = 4 * 128 * 128 * 2;  // 128 KB
    const int SM64  = 4 * 128 * 64 * 2;   //  64 KB
    cudaFuncSetAttribute((const void*)k_gemm_mma<128, true, false, true>,
                         cudaFuncAttributeMaxDynamicSharedMemorySize, SM128);
    cudaFuncSetAttribute((const void*)k_gemm_mma<64, false, true, false>,
                         cudaFuncAttributeMaxDynamicSharedMemorySize, SM64);

    const int scanBlocks = (NN + 255) / 256;  // 118

    // graph preprocessing
    k_detect<<<1, 32>>>((const unsigned int*)ei);
    k_init_cnt<<<scanBlocks, 256>>>();
    k_count<<<(EE + 255) / 256, 256>>>(ei);
    k_scanA<<<scanBlocks, 256>>>();
    k_scanB<<<1, 128>>>(scanBlocks);
    k_scanC<<<scanBlocks, 256>>>();
    k_fill<<<(EN + 255) / 256, 256>>>(ei);

    // weight images + fp16 x
    k_prep_wh<<<(6 * 128 * 16 + 255) / 256, 256>>>(Wh);
    k_prep_w0<<<(128 * 8 + 255) / 256, 256>>>(W0);
    k_x16<<<(NN * 32 + 255) / 256, 256>>>(x);

    const int warpBlocks = (NN * 32 + 255) / 256;   // one warp per node
    const int tcBlocks   = (NN + 127) / 128;        // 235

    // layer 0:  B = (A x) @ W0 + b0      (h0, fp32)
    k_agg64<<<warpBlocks, 256>>>(A);
    k_gemm_mma<64, false, true, false><<<tcBlocks, 256, SM64>>>(A, WI0, b0, B);

    // 6 hidden layers: M16 = leaky(h)@Wh[i] (fp16);  h = A·M16 + bh[i] (fp32, in B)
    for (int i = 0; i < 6; i++) {
        k_gemm_mma<128, true, false, true><<<tcBlocks, 256, SM128>>>(
            B, WIH + (size_t)i * 32768, nullptr, M16);
        k_agg128<<<warpBlocks, 256>>>(M16, bh + (size_t)i * NF, B);
    }

    // output: out = tanh( A (leaky(h) @ Wout) + bout ) * 0.5
    k_gemm3<<<warpBlocks, 256>>>(B, Wout, A);
    k_agg3<<<warpBlocks, 256>>>(A, bout, out);
}

// round 8
// speedup vs baseline: 2.1301x; 1.0233x over previous
#include <cuda_runtime.h>
#include <cuda_bf16.h>
#include <cuda_fp16.h>
#include <math.h>
#include <stdint.h>

#define NN 30000
#define EE 480000
#define EN (EE + NN)
#define NF 128
#define SLOPE 0.02f

// ---------------- scratch (device globals; no allocation allowed) ----------
__device__ int   g_cnt[NN];
__device__ float g_dinv[NN];
__device__ int   g_rowptr[NN + 1];
__device__ int   g_fill[NN];
__device__ int   g_csr_src[EN];
__device__ float g_csr_w[EN];
__device__ float g_bufA[NN * NF];
__device__ float g_bufB[NN * NF];
__device__ __half g_bufM[NN * NF];   // fp16 message buffer (gathered operand)
__device__ __half g_x16[NN * 64];    // fp16 copy of input x
__device__ int   g_is64;
__device__ int   g_bsum[128];
// pre-imaged weights (exact swizzled smem byte layout), bf16 hi/lo planes.
__device__ unsigned short g_wimg_h[6 * 2 * 16384];
__device__ unsigned short g_wimg_0[2 * 8192];

// ---------------- mma/ldmatrix helpers (plain sm_103-safe PTX) -------------
__device__ __forceinline__ uint32_t smem_u32(const void* p) {
    uint32_t a;
    asm("{ .reg .u64 t; cvta.to.shared.u64 t, %1; cvt.u32.u64 %0, t; }"
        : "=r"(a) : "l"(p));
    return a;
}

#define LDSM_X4(r0, r1, r2, r3, addr) \
    asm volatile("ldmatrix.sync.aligned.m8n8.x4.shared.b16 {%0,%1,%2,%3}, [%4];" \
                 : "=r"(r0), "=r"(r1), "=r"(r2), "=r"(r3) : "r"(addr))

#define MMA16816(d, a, b) \
    asm volatile("mma.sync.aligned.m16n8k16.row.col.f32.bf16.bf16.f32 " \
                 "{%0,%1,%2,%3}, {%4,%5,%6,%7}, {%8,%9}, {%0,%1,%2,%3};" \
                 : "+f"((d)[0]), "+f"((d)[1]), "+f"((d)[2]), "+f"((d)[3]) \
                 : "r"((a)[0]), "r"((a)[1]), "r"((a)[2]), "r"((a)[3]), \
                   "r"((b)[0]), "r"((b)[1]))

__device__ __forceinline__ uint32_t pack_pair(float v0, float v1) {
    uint32_t r;
    asm("cvt.rn.bf16x2.f32 %0, %1, %2;" : "=r"(r) : "f"(v1), "f"(v0));
    return r;
}

// fp32x2 from packed half2 word
__device__ __forceinline__ float2 h2f2(uint32_t h) {
    __half2 v = *(__half2*)&h;
    return __half22float2(v);
}

// ---------------- edge-index dtype detection --------------------------------
__global__ void k_detect(const unsigned int* __restrict__ w) {
    int lane = threadIdx.x;
    unsigned bad = 0;
    for (int i = lane; i < 128; i += 32) bad |= w[2 * i + 1];
    #pragma unroll
    for (int o = 16; o > 0; o >>= 1) bad |= __shfl_xor_sync(0xffffffffu, bad, o);
    if (lane == 0) g_is64 = (bad == 0u);
}

__device__ __forceinline__ int edge_at(const void* ei, int idx) {
    return g_is64 ? (int)((const long long*)ei)[idx] : ((const int*)ei)[idx];
}

// ---------------- graph preprocessing ---------------------------------------
__global__ void k_init_cnt() {
    int i = blockIdx.x * blockDim.x + threadIdx.x;
    if (i < NN) g_cnt[i] = 1;
}

__global__ void k_count(const void* __restrict__ ei) {
    int e = blockIdx.x * blockDim.x + threadIdx.x;
    if (e < EE) atomicAdd(&g_cnt[edge_at(ei, EE + e)], 1);
}

__global__ void k_scanA() {
    int i = blockIdx.x * 256 + threadIdx.x;
    int v = (i < NN) ? g_cnt[i] : 0;
    __shared__ int sh[8];
    #pragma unroll
    for (int o = 16; o > 0; o >>= 1) v += __shfl_down_sync(0xffffffffu, v, o);
    if ((threadIdx.x & 31) == 0) sh[threadIdx.x >> 5] = v;
    __syncthreads();
    if (threadIdx.x < 8) {
        int t = sh[threadIdx.x];
        #pragma unroll
        for (int o = 4; o > 0; o >>= 1) t += __shfl_down_sync(0xffu, t, o);
        if (threadIdx.x == 0) g_bsum[blockIdx.x] = t;
    }
}

__global__ void k_scanB(int nblk) {
    __shared__ int sh[128];
    int t = threadIdx.x;
    int v = (t < nblk) ? g_bsum[t] : 0;
    sh[t] = v;
    __syncthreads();
    #pragma unroll
    for (int d = 1; d < 128; d <<= 1) {
        int a = (t >= d) ? sh[t - d] : 0;
        __syncthreads();
        sh[t] += a;
        __syncthreads();
    }
    if (t < nblk) g_bsum[t] = sh[t] - v;
    if (t == 127) g_rowptr[NN] = sh[127];
}

__global__ void k_scanC() {
    __shared__ int sh[256];
    int tid = threadIdx.x;
    int i = blockIdx.x * 256 + tid;
    int v = (i < NN) ? g_cnt[i] : 0;
    sh[tid] = v;
    __syncthreads();
    #pragma unroll
    for (int d = 1; d < 256; d <<= 1) {
        int a = (tid >= d) ? sh[tid - d] : 0;
        __syncthreads();
        sh[tid] += a;
        __syncthreads();
    }
    if (i < NN) {
        int excl = sh[tid] - v + g_bsum[blockIdx.x];
        g_rowptr[i] = excl;
        g_fill[i]   = excl;
        g_dinv[i]   = rsqrtf((float)v);
    }
}

__global__ void k_fill(const void* __restrict__ ei) {
    int e = blockIdx.x * blockDim.x + threadIdx.x;
    if (e < EE) {
        int s = edge_at(ei, e);
        int d = edge_at(ei, EE + e);
        int pos = atomicAdd(&g_fill[d], 1);
        g_csr_src[pos] = s;
        g_csr_w[pos]   = g_dinv[s] * g_dinv[d];
    } else if (e < EN) {
        int i = e - EE;
        int pos = atomicAdd(&g_fill[i], 1);
        float di = g_dinv[i];
        g_csr_src[pos] = i;
        g_csr_w[pos]   = di * di;
    }
}

// convert x to fp16 (once per replay)
__global__ void k_x16(const float* __restrict__ x) {
    int i = blockIdx.x * 256 + threadIdx.x;   // over NN*32 half2
    if (i < NN * 32) {
        float2 v = __ldg((const float2*)(x + 2 * i));
        ((__half2*)g_x16)[i] = __floats2half2_rn(v.x, v.y);
    }
}

// ---------------- weight pre-imaging ----------------------------------------
__global__ void k_prep_wh(const float* __restrict__ Wh) {
    int idx = blockIdx.x * 256 + threadIdx.x;   // 6 layers * 128 f * 16 chunks
    if (idx >= 6 * 128 * 16) return;
    int i = idx / (128 * 16);
    int r = idx % (128 * 16);
    int f = r / 16;
    int chunk = r % 16;
    const float* W = Wh + (size_t)i * 16384;
    float v[8];
    #pragma unroll
    for (int j = 0; j < 8; j++) v[j] = W[(chunk * 8 + j) * 128 + f];
    float h[8];
    #pragma unroll
    for (int j = 0; j < 8; j++) h[j] = __bfloat162float(__float2bfloat16(v[j]));
    uint4 hi = make_uint4(pack_pair(h[0], h[1]), pack_pair(h[2], h[3]),
                          pack_pair(h[4], h[5]), pack_pair(h[6], h[7]));
    uint4 lo = make_uint4(pack_pair(v[0] - h[0], v[1] - h[1]), pack_pair(v[2] - h[2], v[3] - h[3]),
                          pack_pair(v[4] - h[4], v[5] - h[5]), pack_pair(v[6] - h[6], v[7] - h[7]));
    int off = f * 256 + ((chunk ^ (f & 7)) << 4);
    char* base = (char*)g_wimg_h + (size_t)i * 65536;
    *(uint4*)(base + off)         = hi;
    *(uint4*)(base + 32768 + off) = lo;
}

__global__ void k_prep_w0(const float* __restrict__ W0) {
    int idx = blockIdx.x * 256 + threadIdx.x;   // 128 f * 8 chunks (K=64)
    if (idx >= 128 * 8) return;
    int f = idx / 8;
    int chunk = idx % 8;
    float v[8];
    #pragma unroll
    for (int j = 0; j < 8; j++) v[j] = W0[(chunk * 8 + j) * 128 + f];
    float h[8];
    #pragma unroll
    for (int j = 0; j < 8; j++) h[j] = __bfloat162float(__float2bfloat16(v[j]));
    uint4 hi = make_uint4(pack_pair(h[0], h[1]), pack_pair(h[2], h[3]),
                          pack_pair(h[4], h[5]), pack_pair(h[6], h[7]));
    uint4 lo = make_uint4(pack_pair(v[0] - h[0], v[1] - h[1]), pack_pair(v[2] - h[2], v[3] - h[3]),
                          pack_pair(v[4] - h[4], v[5] - h[5]), pack_pair(v[6] - h[6], v[7] - h[7]));
    int off = f * 128 + ((chunk ^ (f & 7)) << 4);
    char* base = (char*)g_wimg_0;
    *(uint4*)(base + off)         = hi;
    *(uint4*)(base + 16384 + off) = lo;
}

// ---------------- tensor GEMM: 128 nodes x 128 outs per block ---------------
template<int K, bool ACT, bool BIAS, bool OUT16>
__global__ void __launch_bounds__(256) k_gemm_mma(const float* __restrict__ H,
                                                  const unsigned short* __restrict__ Wimg,
                                                  const float* __restrict__ bias,
                                                  void* __restrict__ outv) {
    extern __shared__ char smem[];
    constexpr int PITCH  = K * 2;
    constexpr int PBYTES = 128 * PITCH;
    constexpr int OFF_AH = 0;
    constexpr int OFF_AL = PBYTES;
    constexpr int OFF_BH = 2 * PBYTES;
    constexpr int OFF_BL = 3 * PBYTES;
    const int tid  = threadIdx.x;
    const int wid  = tid >> 5;
    const int lane = tid & 31;
    const int node0 = blockIdx.x * 128;
    const uint32_t sb = smem_u32(smem);

    {
        const uint4* src = (const uint4*)Wimg;
        uint4* dst = (uint4*)(smem + OFF_BH);
        #pragma unroll
        for (int i = tid; i < 2 * PBYTES / 16; i += 256) dst[i] = src[i];
    }
    {
        constexpr int NCH = K / 8;
        #pragma unroll
        for (int idx = tid; idx < 128 * NCH; idx += 256) {
            int row = idx / NCH;
            int chunk = idx % NCH;
            int node = node0 + row;
            float4 v0 = make_float4(0.f, 0.f, 0.f, 0.f), v1 = v0;
            if (node < NN) {
                v0 = __ldg((const float4*)(H + (size_t)node * K + chunk * 8));
                v1 = __ldg((const float4*)(H + (size_t)node * K + chunk * 8 + 4));
            }
            float f[8] = {v0.x, v0.y, v0.z, v0.w, v1.x, v1.y, v1.z, v1.w};
            float h[8];
            #pragma unroll
            for (int j = 0; j < 8; j++) {
                float a = f[j];
                if (ACT) a = a > 0.f ? a : a * SLOPE;
                f[j] = a;
                h[j] = __bfloat162float(__float2bfloat16(a));
            }
            uint4 hi = make_uint4(pack_pair(h[0], h[1]), pack_pair(h[2], h[3]),
                                  pack_pair(h[4], h[5]), pack_pair(h[6], h[7]));
            uint4 lo = make_uint4(pack_pair(f[0] - h[0], f[1] - h[1]),
                                  pack_pair(f[2] - h[2], f[3] - h[3]),
                                  pack_pair(f[4] - h[4], f[5] - h[5]),
                                  pack_pair(f[6] - h[6], f[7] - h[7]));
            int off = row * PITCH + ((chunk ^ (row & 7)) << 4);
            *(uint4*)(smem + OFF_AH + off) = hi;
            *(uint4*)(smem + OFF_AL + off) = lo;
        }
    }
    __syncthreads();

    const int mrow0 = (wid & 3) * 32;
    const int ncol0 = (wid >> 2) * 64;
    float acc[2][8][4] = {};

    const uint32_t aOff[3] = {sb + OFF_AH, sb + OFF_AH, sb + OFF_AL};
    const uint32_t bOff[3] = {sb + OFF_BH, sb + OFF_BL, sb + OFF_BH};

    #pragma unroll
    for (int t = 0; t < 3; t++) {
        const uint32_t aB = aOff[t], bB = bOff[t];
        #pragma unroll
        for (int ks = 0; ks < K / 16; ks++) {
            uint32_t a[2][4], b[8][2];
            #pragma unroll
            for (int i = 0; i < 2; i++) {
                int row = mrow0 + i * 16 + (lane & 15);
                int chunk = ks * 2 + (lane >> 4);
                uint32_t addr = aB + row * PITCH + ((chunk ^ (row & 7)) << 4);
                LDSM_X4(a[i][0], a[i][1], a[i][2], a[i][3], addr);
            }
            #pragma unroll
            for (int p = 0; p < 4; p++) {
                int nrow = ncol0 + p * 16 + (lane >> 4) * 8 + (lane & 7);
                int chunk = ks * 2 + ((lane >> 3) & 1);
                uint32_t addr = bB + nrow * PITCH + ((chunk ^ (nrow & 7)) << 4);
                LDSM_X4(b[2 * p][0], b[2 * p][1], b[2 * p + 1][0], b[2 * p + 1][1], addr);
            }
            #pragma unroll
            for (int i = 0; i < 2; i++)
                #pragma unroll
                for (int j = 0; j < 8; j++)
                    MMA16816(acc[i][j], a[i], b[j]);
        }
    }

    #pragma unroll
    for (int i = 0; i < 2; i++) {
        #pragma unroll
        for (int j = 0; j < 8; j++) {
            int c = ncol0 + j * 8 + (lane & 3) * 2;
            float2 bb = make_float2(0.f, 0.f);
            if (BIAS) bb = *(const float2*)(bias + c);
            int r0 = node0 + mrow0 + i * 16 + (lane >> 2);
            int r1 = r0 + 8;
            if (OUT16) {
                __half* o = (__half*)outv;
                if (r0 < NN)
                    *(__half2*)(o + (size_t)r0 * NF + c) =
                        __floats2half2_rn(acc[i][j][0] + bb.x, acc[i][j][1] + bb.y);
                if (r1 < NN)
                    *(__half2*)(o + (size_t)r1 * NF + c) =
                        __floats2half2_rn(acc[i][j][2] + bb.x, acc[i][j][3] + bb.y);
            } else {
                float* o = (float*)outv;
                if (r0 < NN)
                    *(float2*)(o + (size_t)r0 * NF + c) =
                        make_float2(acc[i][j][0] + bb.x, acc[i][j][1] + bb.y);
                if (r1 < NN)
                    *(float2*)(o + (size_t)r1 * NF + c) =
                        make_float2(acc[i][j][2] + bb.x, acc[i][j][3] + bb.y);
            }
        }
    }
}

// ---------------- aggregation kernels (one warp per node) -------------------
__global__ void k_agg64(float* __restrict__ out) {
    int n = (blockIdx.x * blockDim.x + threadIdx.x) >> 5;
    if (n >= NN) return;
    int lane = threadIdx.x & 31;
    int beg = g_rowptr[n], end = g_rowptr[n + 1];
    const __half2* X = (const __half2*)g_x16;
    float2 acc = make_float2(0.f, 0.f);
    int j = beg;
    for (; j + 3 < end; j += 4) {
        int   s0 = g_csr_src[j],   s1 = g_csr_src[j+1],
              s2 = g_csr_src[j+2], s3 = g_csr_src[j+3];
        float w0 = g_csr_w[j],   w1 = g_csr_w[j+1],
              w2 = g_csr_w[j+2], w3 = g_csr_w[j+3];
        float2 v0 = __half22float2(__ldg(X + s0 * 32 + lane));
        float2 v1 = __half22float2(__ldg(X + s1 * 32 + lane));
        float2 v2 = __half22float2(__ldg(X + s2 * 32 + lane));
        float2 v3 = __half22float2(__ldg(X + s3 * 32 + lane));
        acc.x += w0*v0.x + w1*v1.x + w2*v2.x + w3*v3.x;
        acc.y += w0*v0.y + w1*v1.y + w2*v2.y + w3*v3.y;
    }
    for (; j < end; j++) {
        int s = g_csr_src[j]; float w = g_csr_w[j];
        float2 v = __half22float2(__ldg(X + s * 32 + lane));
        acc.x += w * v.x; acc.y += w * v.y;
    }
    *(float2*)(out + n * 64 + lane * 2) = acc;
}

// 128-dim fp16 gather: lane covers 4 features, ONE uint2 (LDG.64) per neighbor
__global__ void k_agg128(const __half* __restrict__ T, const float* __restrict__ bias,
                         float* __restrict__ out) {
    int n = (blockIdx.x * blockDim.x + threadIdx.x) >> 5;
    if (n >= NN) return;
    int lane = threadIdx.x & 31;
    int beg = g_rowptr[n], end = g_rowptr[n + 1];
    const uint2* Tv = (const uint2*)T;   // 4 halves per uint2; row = 32 uint2
    float4 acc = make_float4(0.f, 0.f, 0.f, 0.f);
    int j = beg;
    for (; j + 3 < end; j += 4) {
        int   s0 = g_csr_src[j],   s1 = g_csr_src[j+1],
              s2 = g_csr_src[j+2], s3 = g_csr_src[j+3];
        float w0 = g_csr_w[j],   w1 = g_csr_w[j+1],
              w2 = g_csr_w[j+2], w3 = g_csr_w[j+3];
        uint2 p0 = __ldg(Tv + s0 * 32 + lane);
        uint2 p1 = __ldg(Tv + s1 * 32 + lane);
        uint2 p2 = __ldg(Tv + s2 * 32 + lane);
        uint2 p3 = __ldg(Tv + s3 * 32 + lane);
        float2 a0 = h2f2(p0.x), b0 = h2f2(p0.y);
        float2 a1 = h2f2(p1.x), b1 = h2f2(p1.y);
        float2 a2 = h2f2(p2.x), b2 = h2f2(p2.y);
        float2 a3 = h2f2(p3.x), b3 = h2f2(p3.y);
        acc.x += w0*a0.x + w1*a1.x + w2*a2.x + w3*a3.x;
        acc.y += w0*a0.y + w1*a1.y + w2*a2.y + w3*a3.y;
        acc.z += w0*b0.x + w1*b1.x + w2*b2.x + w3*b3.x;
        acc.w += w0*b0.y + w1*b1.y + w2*b2.y + w3*b3.y;
    }
    for (; j < end; j++) {
        int s = g_csr_src[j]; float w = g_csr_w[j];
        uint2 p = __ldg(Tv + s * 32 + lane);
        float2 a = h2f2(p.x), b = h2f2(p.y);
        acc.x += w*a.x; acc.y += w*a.y; acc.z += w*b.x; acc.w += w*b.y;
    }
    float4 bb = __ldg((const float4*)(bias + lane * 4));
    acc.x += bb.x; acc.y += bb.y; acc.z += bb.z; acc.w += bb.w;
    *(float4*)(out + n * NF + lane * 4) = acc;
}

__global__ void k_agg3(const float* __restrict__ T, const float* __restrict__ bout,
                       float* __restrict__ out) {
    int n = (blockIdx.x * blockDim.x + threadIdx.x) >> 5;
    if (n >= NN) return;
    int lane = threadIdx.x & 31;
    int beg = g_rowptr[n], end = g_rowptr[n + 1];
    float a0 = 0.f, a1 = 0.f, a2 = 0.f;
    for (int j = beg + lane; j < end; j += 32) {
        int s = g_csr_src[j]; float w = g_csr_w[j];
        a0 += w * __ldg(T + s * 3 + 0);
        a1 += w * __ldg(T + s * 3 + 1);
        a2 += w * __ldg(T + s * 3 + 2);
    }
    #pragma unroll
    for (int o = 16; o > 0; o >>= 1) {
        a0 += __shfl_down_sync(0xffffffffu, a0, o);
        a1 += __shfl_down_sync(0xffffffffu, a1, o);
        a2 += __shfl_down_sync(0xffffffffu, a2, o);
    }
    if (lane == 0) {
        out[n * 3 + 0] = tanhf(a0 + __ldg(bout + 0)) * 0.5f;
        out[n * 3 + 1] = tanhf(a1 + __ldg(bout + 1)) * 0.5f;
        out[n * 3 + 2] = tanhf(a2 + __ldg(bout + 2)) * 0.5f;
    }
}

// ---------------- output head -----------------------------------------------
__global__ void k_gemm3(const float* __restrict__ H, const float* __restrict__ W,
                        float* __restrict__ out) {
    int n = (blockIdx.x * blockDim.x + threadIdx.x) >> 5;
    if (n >= NN) return;
    int lane = threadIdx.x & 31;
    float4 h = *(const float4*)(H + (size_t)n * NF + lane * 4);
    h.x = h.x > 0.f ? h.x : h.x * SLOPE;
    h.y = h.y > 0.f ? h.y : h.y * SLOPE;
    h.z = h.z > 0.f ? h.z : h.z * SLOPE;
    h.w = h.w > 0.f ? h.w : h.w * SLOPE;
    float hv[4] = {h.x, h.y, h.z, h.w};
    float a0 = 0.f, a1 = 0.f, a2 = 0.f;
    #pragma unroll
    for (int j = 0; j < 4; j++) {
        int k = lane * 4 + j;
        a0 += hv[j] * __ldg(W + k * 3 + 0);
        a1 += hv[j] * __ldg(W + k * 3 + 1);
        a2 += hv[j] * __ldg(W + k * 3 + 2);
    }
    #pragma unroll
    for (int o = 16; o > 0; o >>= 1) {
        a0 += __shfl_down_sync(0xffffffffu, a0, o);
        a1 += __shfl_down_sync(0xffffffffu, a1, o);
        a2 += __shfl_down_sync(0xffffffffu, a2, o);
    }
    if (lane == 0) {
        out[n * 3 + 0] = a0;
        out[n * 3 + 1] = a1;
        out[n * 3 + 2] = a2;
    }
}

// ---------------- launch -----------------------------------------------------
extern "C" void kernel_launch(void* const* d_in, const int* in_sizes, int n_in,
                              void* d_out, int out_size) {
    const float* x    = (const float*)d_in[0];
    const void*  ei   = d_in[1];
    const float* W0   = (const float*)d_in[2];
    const float* b0   = (const float*)d_in[3];
    const float* Wh   = (const float*)d_in[4];
    const float* bh   = (const float*)d_in[5];
    const float* Wout = (const float*)d_in[6];
    const float* bout = (const float*)d_in[7];
    float* out = (float*)d_out;

    void *pA, *pB, *pM, *pWh, *pW0;
    cudaGetSymbolAddress(&pA, g_bufA);
    cudaGetSymbolAddress(&pB, g_bufB);
    cudaGetSymbolAddress(&pM, g_bufM);
    cudaGetSymbolAddress(&pWh, g_wimg_h);
    cudaGetSymbolAddress(&pW0, g_wimg_0);
    float* A = (float*)pA;
    float* B = (float*)pB;
    __half* M16 = (__half*)pM;
    const unsigned short* WIH = (const unsigned short*)pWh;
    const unsigned short* WI0 = (const unsigned short*)pW0;

    const int SM128 = 4 * 128 * 128 * 2;  // 128 KB
    const int SM64  = 4 * 128 * 64 * 2;   //  64 KB
    cudaFuncSetAttribute((const void*)k_gemm_mma<128, true, false, true>,
                         cudaFuncAttributeMaxDynamicSharedMemorySize, SM128);
    cudaFuncSetAttribute((const void*)k_gemm_mma<64, false, true, false>,
                         cudaFuncAttributeMaxDynamicSharedMemorySize, SM64);

    const int scanBlocks = (NN + 255) / 256;  // 118

    // graph preprocessing
    k_detect<<<1, 32>>>((const unsigned int*)ei);
    k_init_cnt<<<scanBlocks, 256>>>();
    k_count<<<(EE + 255) / 256, 256>>>(ei);
    k_scanA<<<scanBlocks, 256>>>();
    k_scanB<<<1, 128>>>(scanBlocks);
    k_scanC<<<scanBlocks, 256>>>();
    k_fill<<<(EN + 255) / 256, 256>>>(ei);

    // weight images + fp16 x
    k_prep_wh<<<(6 * 128 * 16 + 255) / 256, 256>>>(Wh);
    k_prep_w0<<<(128 * 8 + 255) / 256, 256>>>(W0);
    k_x16<<<(NN * 32 + 255) / 256, 256>>>(x);

    const int warpBlocks = (NN * 32 + 255) / 256;   // one warp per node
    const int tcBlocks   = (NN + 127) / 128;        // 235

    // layer 0:  B = (A x) @ W0 + b0
    k_agg64<<<warpBlocks, 256>>>(A);
    k_gemm_mma<64, false, true, false><<<tcBlocks, 256, SM64>>>(A, WI0, b0, B);

    // 6 hidden layers: M16 = leaky(h)@Wh[i] (fp16);  h = A·M16 + bh[i] (fp32, in B)
    for (int i = 0; i < 6; i++) {
        k_gemm_mma<128, true, false, true><<<tcBlocks, 256, SM128>>>(
            B, WIH + (size_t)i * 32768, nullptr, M16);
        k_agg128<<<warpBlocks, 256>>>(M16, bh + (size_t)i * NF, B);
    }

    // output: out = tanh( A (leaky(h) @ Wout) + bout ) * 0.5
    k_gemm3<<<warpBlocks, 256>>>(B, Wout, A);
    k_agg3<<<warpBlocks, 256>>>(A, bout, out);
}

// round 9
// speedup vs baseline: 2.1505x; 1.0095x over previous
#include <cuda_runtime.h>
#include <cuda_bf16.h>
#include <cuda_fp16.h>
#include <math.h>
#include <stdint.h>

#define NN 30000
#define EE 480000
#define EN (EE + NN)
#define NF 128
#define SLOPE 0.02f

// ---------------- scratch (device globals; no allocation allowed) ----------
__device__ int   g_cnt[NN];
__device__ float g_dinv[NN];
__device__ int   g_rowptr[NN + 1];
__device__ int   g_fill[NN];
__device__ int   g_csr_src[EN];
__device__ float g_csr_w[EN];
__device__ float g_bufA[NN * NF];
__device__ float g_bufB[NN * NF];
__device__ __half g_bufM[NN * NF];   // fp16 message buffer (gathered operand)
__device__ __half g_x16[NN * 64];    // fp16 copy of input x
__device__ int   g_bsum[128];
// pre-imaged weights (exact swizzled smem byte layout), bf16 hi/lo planes.
__device__ unsigned short g_wimg_h[6 * 2 * 16384];
__device__ unsigned short g_wimg_0[2 * 8192];

// ---------------- mma/ldmatrix helpers (plain sm_103-safe PTX) -------------
__device__ __forceinline__ uint32_t smem_u32(const void* p) {
    uint32_t a;
    asm("{ .reg .u64 t; cvta.to.shared.u64 t, %1; cvt.u32.u64 %0, t; }"
        : "=r"(a) : "l"(p));
    return a;
}

#define LDSM_X4(r0, r1, r2, r3, addr) \
    asm volatile("ldmatrix.sync.aligned.m8n8.x4.shared.b16 {%0,%1,%2,%3}, [%4];" \
                 : "=r"(r0), "=r"(r1), "=r"(r2), "=r"(r3) : "r"(addr))

#define MMA16816(d, a, b) \
    asm volatile("mma.sync.aligned.m16n8k16.row.col.f32.bf16.bf16.f32 " \
                 "{%0,%1,%2,%3}, {%4,%5,%6,%7}, {%8,%9}, {%0,%1,%2,%3};" \
                 : "+f"((d)[0]), "+f"((d)[1]), "+f"((d)[2]), "+f"((d)[3]) \
                 : "r"((a)[0]), "r"((a)[1]), "r"((a)[2]), "r"((a)[3]), \
                   "r"((b)[0]), "r"((b)[1]))

__device__ __forceinline__ uint32_t pack_pair(float v0, float v1) {
    uint32_t r;
    asm("cvt.rn.bf16x2.f32 %0, %1, %2;" : "=r"(r) : "f"(v1), "f"(v0));
    return r;
}

__device__ __forceinline__ float2 h2f2(uint32_t h) {
    __half2 v = *(__half2*)&h;
    return __half22float2(v);
}

// per-block inline dtype sniff: int64 edges < 2^31 => odd words of first 128 are 0
__device__ __forceinline__ int sniff_is64(const void* ei, int* s_flag) {
    if (threadIdx.x < 32) {
        const unsigned* w = (const unsigned*)ei;
        unsigned bad = 0;
        for (int i = threadIdx.x; i < 128; i += 32) bad |= w[2 * i + 1];
        #pragma unroll
        for (int o = 16; o > 0; o >>= 1) bad |= __shfl_xor_sync(0xffffffffu, bad, o);
        if (threadIdx.x == 0) *s_flag = (bad == 0u);
    }
    __syncthreads();
    return *s_flag;
}

__device__ __forceinline__ int edge_at2(const void* ei, int idx, int is64) {
    return is64 ? (int)((const long long*)ei)[idx] : ((const int*)ei)[idx];
}

// ---------------- merged prep: cnt init + x16 + weight images ---------------
__global__ void k_prep(const float* __restrict__ x, const float* __restrict__ Wh,
                       const float* __restrict__ W0) {
    int idx = blockIdx.x * 256 + threadIdx.x;
    if (idx < NN * 32) {
        float2 v = __ldg((const float2*)(x + 2 * idx));
        ((__half2*)g_x16)[idx] = __floats2half2_rn(v.x, v.y);
        return;
    }
    idx -= NN * 32;
    if (idx < 6 * 128 * 16) {
        int i = idx / (128 * 16);
        int r = idx % (128 * 16);
        int f = r / 16;
        int chunk = r % 16;
        const float* W = Wh + (size_t)i * 16384;
        float v[8], h[8];
        #pragma unroll
        for (int j = 0; j < 8; j++) {
            v[j] = W[(chunk * 8 + j) * 128 + f];
            h[j] = __bfloat162float(__float2bfloat16(v[j]));
        }
        uint4 hi = make_uint4(pack_pair(h[0], h[1]), pack_pair(h[2], h[3]),
                              pack_pair(h[4], h[5]), pack_pair(h[6], h[7]));
        uint4 lo = make_uint4(pack_pair(v[0]-h[0], v[1]-h[1]), pack_pair(v[2]-h[2], v[3]-h[3]),
                              pack_pair(v[4]-h[4], v[5]-h[5]), pack_pair(v[6]-h[6], v[7]-h[7]));
        int off = f * 256 + ((chunk ^ (f & 7)) << 4);
        char* base = (char*)g_wimg_h + (size_t)i * 65536;
        *(uint4*)(base + off)         = hi;
        *(uint4*)(base + 32768 + off) = lo;
        return;
    }
    idx -= 6 * 128 * 16;
    if (idx < 128 * 8) {
        int f = idx / 8;
        int chunk = idx % 8;
        float v[8], h[8];
        #pragma unroll
        for (int j = 0; j < 8; j++) {
            v[j] = W0[(chunk * 8 + j) * 128 + f];
            h[j] = __bfloat162float(__float2bfloat16(v[j]));
        }
        uint4 hi = make_uint4(pack_pair(h[0], h[1]), pack_pair(h[2], h[3]),
                              pack_pair(h[4], h[5]), pack_pair(h[6], h[7]));
        uint4 lo = make_uint4(pack_pair(v[0]-h[0], v[1]-h[1]), pack_pair(v[2]-h[2], v[3]-h[3]),
                              pack_pair(v[4]-h[4], v[5]-h[5]), pack_pair(v[6]-h[6], v[7]-h[7]));
        int off = f * 128 + ((chunk ^ (f & 7)) << 4);
        char* base = (char*)g_wimg_0;
        *(uint4*)(base + off)         = hi;
        *(uint4*)(base + 16384 + off) = lo;
        return;
    }
    idx -= 128 * 8;
    if (idx < NN) g_cnt[idx] = 1;   // self-loop
}
#define PREP_ITEMS (NN * 32 + 6 * 128 * 16 + 128 * 8 + NN)

// ---------------- graph preprocessing ---------------------------------------
__global__ void k_count(const void* __restrict__ ei) {
    __shared__ int s64;
    int is64 = sniff_is64(ei, &s64);
    int e = blockIdx.x * blockDim.x + threadIdx.x;
    if (e < EE) atomicAdd(&g_cnt[edge_at2(ei, EE + e, is64)], 1);
}

__global__ void k_scanA() {
    int i = blockIdx.x * 256 + threadIdx.x;
    int v = (i < NN) ? g_cnt[i] : 0;
    __shared__ int sh[8];
    #pragma unroll
    for (int o = 16; o > 0; o >>= 1) v += __shfl_down_sync(0xffffffffu, v, o);
    if ((threadIdx.x & 31) == 0) sh[threadIdx.x >> 5] = v;
    __syncthreads();
    if (threadIdx.x < 8) {
        int t = sh[threadIdx.x];
        #pragma unroll
        for (int o = 4; o > 0; o >>= 1) t += __shfl_down_sync(0xffu, t, o);
        if (threadIdx.x == 0) g_bsum[blockIdx.x] = t;
    }
}

// merged scanB+scanC: each block computes its own base from the 118 partials
__global__ void k_scanC(int nblk) {
    __shared__ int sh[256];
    __shared__ int sbs[128];
    __shared__ int s_base;
    const int tid = threadIdx.x;
    const int bid = blockIdx.x;
    if (tid < nblk) sbs[tid] = g_bsum[tid];
    __syncthreads();
    if (tid < 32) {
        int p = 0;
        for (int j = tid; j < bid; j += 32) p += sbs[j];
        #pragma unroll
        for (int o = 16; o > 0; o >>= 1) p += __shfl_down_sync(0xffffffffu, p, o);
        if (tid == 0) s_base = p;
    }
    int i = bid * 256 + tid;
    int v = (i < NN) ? g_cnt[i] : 0;
    sh[tid] = v;
    __syncthreads();
    #pragma unroll
    for (int d = 1; d < 256; d <<= 1) {
        int a = (tid >= d) ? sh[tid - d] : 0;
        __syncthreads();
        sh[tid] += a;
        __syncthreads();
    }
    if (i < NN) {
        int excl = sh[tid] - v + s_base;
        g_rowptr[i] = excl;
        g_fill[i]   = excl;
        g_dinv[i]   = rsqrtf((float)v);
        if (i == NN - 1) g_rowptr[NN] = excl + v;
    }
}

__global__ void k_fill(const void* __restrict__ ei) {
    __shared__ int s64;
    int is64 = sniff_is64(ei, &s64);
    int e = blockIdx.x * blockDim.x + threadIdx.x;
    if (e < EE) {
        int s = edge_at2(ei, e, is64);
        int d = edge_at2(ei, EE + e, is64);
        int pos = atomicAdd(&g_fill[d], 1);
        g_csr_src[pos] = s;
        g_csr_w[pos]   = g_dinv[s] * g_dinv[d];
    } else if (e < EN) {
        int i = e - EE;
        int pos = atomicAdd(&g_fill[i], 1);
        float di = g_dinv[i];
        g_csr_src[pos] = i;
        g_csr_w[pos]   = di * di;
    }
}

// ---------------- tensor GEMM: 2 x (128 nodes x 128 outs) per block ---------
// W image staged once per block, reused across both node tiles.
template<int K, bool ACT, bool BIAS, bool OUT16>
__global__ void __launch_bounds__(256) k_gemm_mma(const float* __restrict__ H,
                                                  const unsigned short* __restrict__ Wimg,
                                                  const float* __restrict__ bias,
                                                  void* __restrict__ outv) {
    extern __shared__ char smem[];
    constexpr int PITCH  = K * 2;
    constexpr int PBYTES = 128 * PITCH;
    constexpr int OFF_AH = 0;
    constexpr int OFF_AL = PBYTES;
    constexpr int OFF_BH = 2 * PBYTES;
    constexpr int OFF_BL = 3 * PBYTES;
    const int tid  = threadIdx.x;
    const int wid  = tid >> 5;
    const int lane = tid & 31;
    const uint32_t sb = smem_u32(smem);

    // stage W once (hi + lo planes, contiguous)
    {
        const uint4* src = (const uint4*)Wimg;
        uint4* dst = (uint4*)(smem + OFF_BH);
        #pragma unroll
        for (int i = tid; i < 2 * PBYTES / 16; i += 256) dst[i] = src[i];
    }

    const int mrow0 = (wid & 3) * 32;
    const int ncol0 = (wid >> 2) * 64;
    const uint32_t aOff[3] = {sb + OFF_AH, sb + OFF_AH, sb + OFF_AL};
    const uint32_t bOff[3] = {sb + OFF_BH, sb + OFF_BL, sb + OFF_BH};

    #pragma unroll
    for (int half = 0; half < 2; half++) {
        const int node0 = (blockIdx.x * 2 + half) * 128;
        if (node0 >= NN) break;
        __syncthreads();   // prior ldsm reads done (and W staged) before A overwrite

        // stage A tile: 128 rows x K, activation + bf16 hi/lo split + swizzle
        {
            constexpr int NCH = K / 8;
            #pragma unroll
            for (int idx = tid; idx < 128 * NCH; idx += 256) {
                int row = idx / NCH;
                int chunk = idx % NCH;
                int node = node0 + row;
                float4 v0 = make_float4(0.f, 0.f, 0.f, 0.f), v1 = v0;
                if (node < NN) {
                    v0 = __ldg((const float4*)(H + (size_t)node * K + chunk * 8));
                    v1 = __ldg((const float4*)(H + (size_t)node * K + chunk * 8 + 4));
                }
                float f[8] = {v0.x, v0.y, v0.z, v0.w, v1.x, v1.y, v1.z, v1.w};
                float h[8];
                #pragma unroll
                for (int j = 0; j < 8; j++) {
                    float a = f[j];
                    if (ACT) a = a > 0.f ? a : a * SLOPE;
                    f[j] = a;
                    h[j] = __bfloat162float(__float2bfloat16(a));
                }
                uint4 hi = make_uint4(pack_pair(h[0], h[1]), pack_pair(h[2], h[3]),
                                      pack_pair(h[4], h[5]), pack_pair(h[6], h[7]));
                uint4 lo = make_uint4(pack_pair(f[0]-h[0], f[1]-h[1]),
                                      pack_pair(f[2]-h[2], f[3]-h[3]),
                                      pack_pair(f[4]-h[4], f[5]-h[5]),
                                      pack_pair(f[6]-h[6], f[7]-h[7]));
                int off = row * PITCH + ((chunk ^ (row & 7)) << 4);
                *(uint4*)(smem + OFF_AH + off) = hi;
                *(uint4*)(smem + OFF_AL + off) = lo;
            }
        }
        __syncthreads();

        float acc[2][8][4] = {};
        #pragma unroll
        for (int t = 0; t < 3; t++) {
            const uint32_t aB = aOff[t], bB = bOff[t];
            #pragma unroll
            for (int ks = 0; ks < K / 16; ks++) {
                uint32_t a[2][4], b[8][2];
                #pragma unroll
                for (int i = 0; i < 2; i++) {
                    int row = mrow0 + i * 16 + (lane & 15);
                    int chunk = ks * 2 + (lane >> 4);
                    uint32_t addr = aB + row * PITCH + ((chunk ^ (row & 7)) << 4);
                    LDSM_X4(a[i][0], a[i][1], a[i][2], a[i][3], addr);
                }
                #pragma unroll
                for (int p = 0; p < 4; p++) {
                    int nrow = ncol0 + p * 16 + (lane >> 4) * 8 + (lane & 7);
                    int chunk = ks * 2 + ((lane >> 3) & 1);
                    uint32_t addr = bB + nrow * PITCH + ((chunk ^ (nrow & 7)) << 4);
                    LDSM_X4(b[2*p][0], b[2*p][1], b[2*p+1][0], b[2*p+1][1], addr);
                }
                #pragma unroll
                for (int i = 0; i < 2; i++)
                    #pragma unroll
                    for (int j = 0; j < 8; j++)
                        MMA16816(acc[i][j], a[i], b[j]);
            }
        }

        #pragma unroll
        for (int i = 0; i < 2; i++) {
            #pragma unroll
            for (int j = 0; j < 8; j++) {
                int c = ncol0 + j * 8 + (lane & 3) * 2;
                float2 bb = make_float2(0.f, 0.f);
                if (BIAS) bb = *(const float2*)(bias + c);
                int r0 = node0 + mrow0 + i * 16 + (lane >> 2);
                int r1 = r0 + 8;
                if (OUT16) {
                    __half* o = (__half*)outv;
                    if (r0 < NN)
                        *(__half2*)(o + (size_t)r0 * NF + c) =
                            __floats2half2_rn(acc[i][j][0] + bb.x, acc[i][j][1] + bb.y);
                    if (r1 < NN)
                        *(__half2*)(o + (size_t)r1 * NF + c) =
                            __floats2half2_rn(acc[i][j][2] + bb.x, acc[i][j][3] + bb.y);
                } else {
                    float* o = (float*)outv;
                    if (r0 < NN)
                        *(float2*)(o + (size_t)r0 * NF + c) =
                            make_float2(acc[i][j][0] + bb.x, acc[i][j][1] + bb.y);
                    if (r1 < NN)
                        *(float2*)(o + (size_t)r1 * NF + c) =
                            make_float2(acc[i][j][2] + bb.x, acc[i][j][3] + bb.y);
                }
            }
        }
    }
}

// ---------------- aggregation kernels (one warp per node) -------------------
__global__ void k_agg64(float* __restrict__ out) {
    int n = (blockIdx.x * blockDim.x + threadIdx.x) >> 5;
    if (n >= NN) return;
    int lane = threadIdx.x & 31;
    int beg = g_rowptr[n], end = g_rowptr[n + 1];
    const __half2* X = (const __half2*)g_x16;
    float2 acc = make_float2(0.f, 0.f);
    int j = beg;
    for (; j + 3 < end; j += 4) {
        int   s0 = g_csr_src[j],   s1 = g_csr_src[j+1],
              s2 = g_csr_src[j+2], s3 = g_csr_src[j+3];
        float w0 = g_csr_w[j],   w1 = g_csr_w[j+1],
              w2 = g_csr_w[j+2], w3 = g_csr_w[j+3];
        float2 v0 = __half22float2(__ldg(X + s0 * 32 + lane));
        float2 v1 = __half22float2(__ldg(X + s1 * 32 + lane));
        float2 v2 = __half22float2(__ldg(X + s2 * 32 + lane));
        float2 v3 = __half22float2(__ldg(X + s3 * 32 + lane));
        acc.x += w0*v0.x + w1*v1.x + w2*v2.x + w3*v3.x;
        acc.y += w0*v0.y + w1*v1.y + w2*v2.y + w3*v3.y;
    }
    for (; j < end; j++) {
        int s = g_csr_src[j]; float w = g_csr_w[j];
        float2 v = __half22float2(__ldg(X + s * 32 + lane));
        acc.x += w * v.x; acc.y += w * v.y;
    }
    *(float2*)(out + n * 64 + lane * 2) = acc;
}

__global__ void k_agg128(const __half* __restrict__ T, const float* __restrict__ bias,
                         float* __restrict__ out) {
    int n = (blockIdx.x * blockDim.x + threadIdx.x) >> 5;
    if (n >= NN) return;
    int lane = threadIdx.x & 31;
    int beg = g_rowptr[n], end = g_rowptr[n + 1];
    const uint2* Tv = (const uint2*)T;
    float4 acc = make_float4(0.f, 0.f, 0.f, 0.f);
    int j = beg;
    for (; j + 3 < end; j += 4) {
        int   s0 = g_csr_src[j],   s1 = g_csr_src[j+1],
              s2 = g_csr_src[j+2], s3 = g_csr_src[j+3];
        float w0 = g_csr_w[j],   w1 = g_csr_w[j+1],
              w2 = g_csr_w[j+2], w3 = g_csr_w[j+3];
        uint2 p0 = __ldg(Tv + s0 * 32 + lane);
        uint2 p1 = __ldg(Tv + s1 * 32 + lane);
        uint2 p2 = __ldg(Tv + s2 * 32 + lane);
        uint2 p3 = __ldg(Tv + s3 * 32 + lane);
        float2 a0 = h2f2(p0.x), b0 = h2f2(p0.y);
        float2 a1 = h2f2(p1.x), b1 = h2f2(p1.y);
        float2 a2 = h2f2(p2.x), b2 = h2f2(p2.y);
        float2 a3 = h2f2(p3.x), b3 = h2f2(p3.y);
        acc.x += w0*a0.x + w1*a1.x + w2*a2.x + w3*a3.x;
        acc.y += w0*a0.y + w1*a1.y + w2*a2.y + w3*a3.y;
        acc.z += w0*b0.x + w1*b1.x + w2*b2.x + w3*b3.x;
        acc.w += w0*b0.y + w1*b1.y + w2*b2.y + w3*b3.y;
    }
    for (; j < end; j++) {
        int s = g_csr_src[j]; float w = g_csr_w[j];
        uint2 p = __ldg(Tv + s * 32 + lane);
        float2 a = h2f2(p.x), b = h2f2(p.y);
        acc.x += w*a.x; acc.y += w*a.y; acc.z += w*b.x; acc.w += w*b.y;
    }
    float4 bb = __ldg((const float4*)(bias + lane * 4));
    acc.x += bb.x; acc.y += bb.y; acc.z += bb.z; acc.w += bb.w;
    *(float4*)(out + n * NF + lane * 4) = acc;
}

__global__ void k_agg3(const float* __restrict__ T, const float* __restrict__ bout,
                       float* __restrict__ out) {
    int n = (blockIdx.x * blockDim.x + threadIdx.x) >> 5;
    if (n >= NN) return;
    int lane = threadIdx.x & 31;
    int beg = g_rowptr[n], end = g_rowptr[n + 1];
    float a0 = 0.f, a1 = 0.f, a2 = 0.f;
    for (int j = beg + lane; j < end; j += 32) {
        int s = g_csr_src[j]; float w = g_csr_w[j];
        a0 += w * __ldg(T + s * 3 + 0);
        a1 += w * __ldg(T + s * 3 + 1);
        a2 += w * __ldg(T + s * 3 + 2);
    }
    #pragma unroll
    for (int o = 16; o > 0; o >>= 1) {
        a0 += __shfl_down_sync(0xffffffffu, a0, o);
        a1 += __shfl_down_sync(0xffffffffu, a1, o);
        a2 += __shfl_down_sync(0xffffffffu, a2, o);
    }
    if (lane == 0) {
        out[n * 3 + 0] = tanhf(a0 + __ldg(bout + 0)) * 0.5f;
        out[n * 3 + 1] = tanhf(a1 + __ldg(bout + 1)) * 0.5f;
        out[n * 3 + 2] = tanhf(a2 + __ldg(bout + 2)) * 0.5f;
    }
}

// ---------------- output head -----------------------------------------------
__global__ void k_gemm3(const float* __restrict__ H, const float* __restrict__ W,
                        float* __restrict__ out) {
    int n = (blockIdx.x * blockDim.x + threadIdx.x) >> 5;
    if (n >= NN) return;
    int lane = threadIdx.x & 31;
    float4 h = *(const float4*)(H + (size_t)n * NF + lane * 4);
    h.x = h.x > 0.f ? h.x : h.x * SLOPE;
    h.y = h.y > 0.f ? h.y : h.y * SLOPE;
    h.z = h.z > 0.f ? h.z : h.z * SLOPE;
    h.w = h.w > 0.f ? h.w : h.w * SLOPE;
    float hv[4] = {h.x, h.y, h.z, h.w};
    float a0 = 0.f, a1 = 0.f, a2 = 0.f;
    #pragma unroll
    for (int j = 0; j < 4; j++) {
        int k = lane * 4 + j;
        a0 += hv[j] * __ldg(W + k * 3 + 0);
        a1 += hv[j] * __ldg(W + k * 3 + 1);
        a2 += hv[j] * __ldg(W + k * 3 + 2);
    }
    #pragma unroll
    for (int o = 16; o > 0; o >>= 1) {
        a0 += __shfl_down_sync(0xffffffffu, a0, o);
        a1 += __shfl_down_sync(0xffffffffu, a1, o);
        a2 += __shfl_down_sync(0xffffffffu, a2, o);
    }
    if (lane == 0) {
        out[n * 3 + 0] = a0;
        out[n * 3 + 1] = a1;
        out[n * 3 + 2] = a2;
    }
}

// ---------------- launch -----------------------------------------------------
extern "C" void kernel_launch(void* const* d_in, const int* in_sizes, int n_in,
                              void* d_out, int out_size) {
    const float* x    = (const float*)d_in[0];
    const void*  ei   = d_in[1];
    const float* W0   = (const float*)d_in[2];
    const float* b0   = (const float*)d_in[3];
    const float* Wh   = (const float*)d_in[4];
    const float* bh   = (const float*)d_in[5];
    const float* Wout = (const float*)d_in[6];
    const float* bout = (const float*)d_in[7];
    float* out = (float*)d_out;

    void *pA, *pB, *pM, *pWh, *pW0;
    cudaGetSymbolAddress(&pA, g_bufA);
    cudaGetSymbolAddress(&pB, g_bufB);
    cudaGetSymbolAddress(&pM, g_bufM);
    cudaGetSymbolAddress(&pWh, g_wimg_h);
    cudaGetSymbolAddress(&pW0, g_wimg_0);
    float* A = (float*)pA;
    float* B = (float*)pB;
    __half* M16 = (__half*)pM;
    const unsigned short* WIH = (const unsigned short*)pWh;
    const unsigned short* WI0 = (const unsigned short*)pW0;

    const int SM128 = 4 * 128 * 128 * 2;  // 128 KB
    const int SM64  = 4 * 128 * 64 * 2;   //  64 KB
    cudaFuncSetAttribute((const void*)k_gemm_mma<128, true, false, true>,
                         cudaFuncAttributeMaxDynamicSharedMemorySize, SM128);
    cudaFuncSetAttribute((const void*)k_gemm_mma<64, false, true, false>,
                         cudaFuncAttributeMaxDynamicSharedMemorySize, SM64);

    const int scanBlocks = (NN + 255) / 256;  // 118

    // prep (cnt init + x16 + weight images), then graph preprocessing
    k_prep<<<(PREP_ITEMS + 255) / 256, 256>>>(x, Wh, W0);
    k_count<<<(EE + 255) / 256, 256>>>(ei);
    k_scanA<<<scanBlocks, 256>>>();
    k_scanC<<<scanBlocks, 256>>>(scanBlocks);
    k_fill<<<(EN + 255) / 256, 256>>>(ei);

    const int warpBlocks = (NN * 32 + 255) / 256;   // one warp per node
    const int tcBlocks   = (NN + 255) / 256;        // 118 (2 tiles per block)

    // layer 0:  B = (A x) @ W0 + b0
    k_agg64<<<warpBlocks, 256>>>(A);
    k_gemm_mma<64, false, true, false><<<tcBlocks, 256, SM64>>>(A, WI0, b0, B);

    // 6 hidden layers: M16 = leaky(h)@Wh[i] (fp16);  h = A·M16 + bh[i] (fp32, in B)
    for (int i = 0; i < 6; i++) {
        k_gemm_mma<128, true, false, true><<<tcBlocks, 256, SM128>>>(
            B, WIH + (size_t)i * 32768, nullptr, M16);
        k_agg128<<<warpBlocks, 256>>>(M16, bh + (size_t)i * NF, B);
    }

    // output: out = tanh( A (leaky(h) @ Wout) + bout ) * 0.5
    k_gemm3<<<warpBlocks, 256>>>(B, Wout, A);
    k_agg3<<<warpBlocks, 256>>>(A, bout, out);
}

// round 10
// speedup vs baseline: 2.4102x; 1.1208x over previous
#include <cuda_runtime.h>
#include <cuda_fp16.h>
#include <math.h>
#include <stdint.h>

#define NN 30000
#define EE 480000
#define EN (EE + NN)
#define NF 128
#define SLOPE 0.02f

// ---------------- scratch (device globals; no allocation allowed) ----------
__device__ int   g_cnt[NN];
__device__ float g_dinv[NN];
__device__ int   g_rowptr[NN + 1];
__device__ int   g_fill[NN];
__device__ int   g_csr_src[EN];
__device__ float g_csr_w[EN];
__device__ float g_bufA[NN * NF];
__device__ float g_bufB[NN * NF];
__device__ __half g_bufM[NN * NF];   // fp16 message buffer (gathered operand)
__device__ __half g_x16[NN * 64];    // fp16 copy of input x
__device__ int   g_bsum[128];
// pre-imaged weights (exact swizzled smem byte layout), fp16 hi/lo planes.
__device__ unsigned short g_wimg_h[6 * 2 * 16384];
__device__ unsigned short g_wimg_0[2 * 8192];

// ---------------- mma/ldmatrix helpers (plain sm_103-safe PTX) -------------
__device__ __forceinline__ uint32_t smem_u32(const void* p) {
    uint32_t a;
    asm("{ .reg .u64 t; cvta.to.shared.u64 t, %1; cvt.u32.u64 %0, t; }"
        : "=r"(a) : "l"(p));
    return a;
}

#define LDSM_X4(r0, r1, r2, r3, addr) \
    asm volatile("ldmatrix.sync.aligned.m8n8.x4.shared.b16 {%0,%1,%2,%3}, [%4];" \
                 : "=r"(r0), "=r"(r1), "=r"(r2), "=r"(r3) : "r"(addr))

#define MMA16816F16(d, a, b) \
    asm volatile("mma.sync.aligned.m16n8k16.row.col.f32.f16.f16.f32 " \
                 "{%0,%1,%2,%3}, {%4,%5,%6,%7}, {%8,%9}, {%0,%1,%2,%3};" \
                 : "+f"((d)[0]), "+f"((d)[1]), "+f"((d)[2]), "+f"((d)[3]) \
                 : "r"((a)[0]), "r"((a)[1]), "r"((a)[2]), "r"((a)[3]), \
                   "r"((b)[0]), "r"((b)[1]))

__device__ __forceinline__ uint32_t packh2(float a, float b) {
    __half2 h = __floats2half2_rn(a, b);
    return *(uint32_t*)&h;
}

__device__ __forceinline__ float2 h2f2(uint32_t h) {
    __half2 v = *(__half2*)&h;
    return __half22float2(v);
}

// per-block inline dtype sniff: int64 edges < 2^31 => odd words of first 128 are 0
__device__ __forceinline__ int sniff_is64(const void* ei, int* s_flag) {
    if (threadIdx.x < 32) {
        const unsigned* w = (const unsigned*)ei;
        unsigned bad = 0;
        for (int i = threadIdx.x; i < 128; i += 32) bad |= w[2 * i + 1];
        #pragma unroll
        for (int o = 16; o > 0; o >>= 1) bad |= __shfl_xor_sync(0xffffffffu, bad, o);
        if (threadIdx.x == 0) *s_flag = (bad == 0u);
    }
    __syncthreads();
    return *s_flag;
}

__device__ __forceinline__ int edge_at2(const void* ei, int idx, int is64) {
    return is64 ? (int)((const long long*)ei)[idx] : ((const int*)ei)[idx];
}

// ---------------- merged prep: cnt init + x16 + weight images ---------------
// W imaged as fp16 hi + fp16 lo (lo = fp16(w - hi)): 22-bit combined mantissa.
__global__ void k_prep(const float* __restrict__ x, const float* __restrict__ Wh,
                       const float* __restrict__ W0) {
    int idx = blockIdx.x * 256 + threadIdx.x;
    if (idx < NN * 32) {
        float2 v = __ldg((const float2*)(x + 2 * idx));
        ((__half2*)g_x16)[idx] = __floats2half2_rn(v.x, v.y);
        return;
    }
    idx -= NN * 32;
    if (idx < 6 * 128 * 16) {
        int i = idx / (128 * 16);
        int r = idx % (128 * 16);
        int f = r / 16;
        int chunk = r % 16;
        const float* W = Wh + (size_t)i * 16384;
        float v[8], h[8];
        #pragma unroll
        for (int j = 0; j < 8; j++) {
            v[j] = W[(chunk * 8 + j) * 128 + f];
            h[j] = __half2float(__float2half_rn(v[j]));
        }
        uint4 hi = make_uint4(packh2(h[0], h[1]), packh2(h[2], h[3]),
                              packh2(h[4], h[5]), packh2(h[6], h[7]));
        uint4 lo = make_uint4(packh2(v[0]-h[0], v[1]-h[1]), packh2(v[2]-h[2], v[3]-h[3]),
                              packh2(v[4]-h[4], v[5]-h[5]), packh2(v[6]-h[6], v[7]-h[7]));
        int off = f * 256 + ((chunk ^ (f & 7)) << 4);
        char* base = (char*)g_wimg_h + (size_t)i * 65536;
        *(uint4*)(base + off)         = hi;
        *(uint4*)(base + 32768 + off) = lo;
        return;
    }
    idx -= 6 * 128 * 16;
    if (idx < 128 * 8) {
        int f = idx / 8;
        int chunk = idx % 8;
        float v[8], h[8];
        #pragma unroll
        for (int j = 0; j < 8; j++) {
            v[j] = W0[(chunk * 8 + j) * 128 + f];
            h[j] = __half2float(__float2half_rn(v[j]));
        }
        uint4 hi = make_uint4(packh2(h[0], h[1]), packh2(h[2], h[3]),
                              packh2(h[4], h[5]), packh2(h[6], h[7]));
        uint4 lo = make_uint4(packh2(v[0]-h[0], v[1]-h[1]), packh2(v[2]-h[2], v[3]-h[3]),
                              packh2(v[4]-h[4], v[5]-h[5]), packh2(v[6]-h[6], v[7]-h[7]));
        int off = f * 128 + ((chunk ^ (f & 7)) << 4);
        char* base = (char*)g_wimg_0;
        *(uint4*)(base + off)         = hi;
        *(uint4*)(base + 16384 + off) = lo;
        return;
    }
    idx -= 128 * 8;
    if (idx < NN) g_cnt[idx] = 1;   // self-loop
}
#define PREP_ITEMS (NN * 32 + 6 * 128 * 16 + 128 * 8 + NN)

// ---------------- graph preprocessing ---------------------------------------
__global__ void k_count(const void* __restrict__ ei) {
    __shared__ int s64;
    int is64 = sniff_is64(ei, &s64);
    int e = blockIdx.x * blockDim.x + threadIdx.x;
    if (e < EE) atomicAdd(&g_cnt[edge_at2(ei, EE + e, is64)], 1);
}

__global__ void k_scanA() {
    int i = blockIdx.x * 256 + threadIdx.x;
    int v = (i < NN) ? g_cnt[i] : 0;
    __shared__ int sh[8];
    #pragma unroll
    for (int o = 16; o > 0; o >>= 1) v += __shfl_down_sync(0xffffffffu, v, o);
    if ((threadIdx.x & 31) == 0) sh[threadIdx.x >> 5] = v;
    __syncthreads();
    if (threadIdx.x < 8) {
        int t = sh[threadIdx.x];
        #pragma unroll
        for (int o = 4; o > 0; o >>= 1) t += __shfl_down_sync(0xffu, t, o);
        if (threadIdx.x == 0) g_bsum[blockIdx.x] = t;
    }
}

__global__ void k_scanC(int nblk) {
    __shared__ int sh[256];
    __shared__ int sbs[128];
    __shared__ int s_base;
    const int tid = threadIdx.x;
    const int bid = blockIdx.x;
    if (tid < nblk) sbs[tid] = g_bsum[tid];
    __syncthreads();
    if (tid < 32) {
        int p = 0;
        for (int j = tid; j < bid; j += 32) p += sbs[j];
        #pragma unroll
        for (int o = 16; o > 0; o >>= 1) p += __shfl_down_sync(0xffffffffu, p, o);
        if (tid == 0) s_base = p;
    }
    int i = bid * 256 + tid;
    int v = (i < NN) ? g_cnt[i] : 0;
    sh[tid] = v;
    __syncthreads();
    #pragma unroll
    for (int d = 1; d < 256; d <<= 1) {
        int a = (tid >= d) ? sh[tid - d] : 0;
        __syncthreads();
        sh[tid] += a;
        __syncthreads();
    }
    if (i < NN) {
        int excl = sh[tid] - v + s_base;
        g_rowptr[i] = excl;
        g_fill[i]   = excl;
        g_dinv[i]   = rsqrtf((float)v);
        if (i == NN - 1) g_rowptr[NN] = excl + v;
    }
}

__global__ void k_fill(const void* __restrict__ ei) {
    __shared__ int s64;
    int is64 = sniff_is64(ei, &s64);
    int e = blockIdx.x * blockDim.x + threadIdx.x;
    if (e < EE) {
        int s = edge_at2(ei, e, is64);
        int d = edge_at2(ei, EE + e, is64);
        int pos = atomicAdd(&g_fill[d], 1);
        g_csr_src[pos] = s;
        g_csr_w[pos]   = g_dinv[s] * g_dinv[d];
    } else if (e < EN) {
        int i = e - EE;
        int pos = atomicAdd(&g_fill[i], 1);
        float di = g_dinv[i];
        g_csr_src[pos] = i;
        g_csr_w[pos]   = di * di;
    }
}

// ---------------- tensor GEMM: 128 nodes x 128 outs per block ---------------
// A = fp16 (no split), W = fp16 hi/lo planes: D = A*Wh + A*Wl (fp32 accum).
template<int K, bool ACT, bool BIAS, bool OUT16>
__global__ void __launch_bounds__(256) k_gemm_mma(const float* __restrict__ H,
                                                  const unsigned short* __restrict__ Wimg,
                                                  const float* __restrict__ bias,
                                                  void* __restrict__ outv) {
    extern __shared__ char smem[];
    constexpr int PITCH  = K * 2;
    constexpr int PBYTES = 128 * PITCH;
    constexpr int OFF_A  = 0;
    constexpr int OFF_BH = PBYTES;
    constexpr int OFF_BL = 2 * PBYTES;
    const int tid  = threadIdx.x;
    const int wid  = tid >> 5;
    const int lane = tid & 31;
    const int node0 = blockIdx.x * 128;
    const uint32_t sb = smem_u32(smem);

    // stage W (hi + lo planes, contiguous in gmem image)
    {
        const uint4* src = (const uint4*)Wimg;
        uint4* dst = (uint4*)(smem + OFF_BH);
        #pragma unroll
        for (int i = tid; i < 2 * PBYTES / 16; i += 256) dst[i] = src[i];
    }
    // stage A: 128 rows x K fp32 -> fp16, activation fused, swizzled chunks
    {
        constexpr int NCH = K / 8;
        #pragma unroll
        for (int idx = tid; idx < 128 * NCH; idx += 256) {
            int row = idx / NCH;
            int chunk = idx % NCH;
            int node = node0 + row;
            float4 v0 = make_float4(0.f, 0.f, 0.f, 0.f), v1 = v0;
            if (node < NN) {
                v0 = __ldg((const float4*)(H + (size_t)node * K + chunk * 8));
                v1 = __ldg((const float4*)(H + (size_t)node * K + chunk * 8 + 4));
            }
            if (ACT) {
                v0.x = v0.x > 0.f ? v0.x : v0.x * SLOPE;
                v0.y = v0.y > 0.f ? v0.y : v0.y * SLOPE;
                v0.z = v0.z > 0.f ? v0.z : v0.z * SLOPE;
                v0.w = v0.w > 0.f ? v0.w : v0.w * SLOPE;
                v1.x = v1.x > 0.f ? v1.x : v1.x * SLOPE;
                v1.y = v1.y > 0.f ? v1.y : v1.y * SLOPE;
                v1.z = v1.z > 0.f ? v1.z : v1.z * SLOPE;
                v1.w = v1.w > 0.f ? v1.w : v1.w * SLOPE;
            }
            uint4 a16 = make_uint4(packh2(v0.x, v0.y), packh2(v0.z, v0.w),
                                   packh2(v1.x, v1.y), packh2(v1.z, v1.w));
            int off = row * PITCH + ((chunk ^ (row & 7)) << 4);
            *(uint4*)(smem + OFF_A + off) = a16;
        }
    }
    __syncthreads();

    const int mrow0 = (wid & 3) * 32;
    const int ncol0 = (wid >> 2) * 64;
    float acc[2][8][4] = {};
    const uint32_t aB = sb + OFF_A;
    const uint32_t bOff[2] = {sb + OFF_BH, sb + OFF_BL};

    #pragma unroll
    for (int t = 0; t < 2; t++) {
        const uint32_t bB = bOff[t];
        #pragma unroll
        for (int ks = 0; ks < K / 16; ks++) {
            uint32_t a[2][4], b[8][2];
            #pragma unroll
            for (int i = 0; i < 2; i++) {
                int row = mrow0 + i * 16 + (lane & 15);
                int chunk = ks * 2 + (lane >> 4);
                uint32_t addr = aB + row * PITCH + ((chunk ^ (row & 7)) << 4);
                LDSM_X4(a[i][0], a[i][1], a[i][2], a[i][3], addr);
            }
            #pragma unroll
            for (int p = 0; p < 4; p++) {
                int nrow = ncol0 + p * 16 + (lane >> 4) * 8 + (lane & 7);
                int chunk = ks * 2 + ((lane >> 3) & 1);
                uint32_t addr = bB + nrow * PITCH + ((chunk ^ (nrow & 7)) << 4);
                LDSM_X4(b[2*p][0], b[2*p][1], b[2*p+1][0], b[2*p+1][1], addr);
            }
            #pragma unroll
            for (int i = 0; i < 2; i++)
                #pragma unroll
                for (int j = 0; j < 8; j++)
                    MMA16816F16(acc[i][j], a[i], b[j]);
        }
    }

    #pragma unroll
    for (int i = 0; i < 2; i++) {
        #pragma unroll
        for (int j = 0; j < 8; j++) {
            int c = ncol0 + j * 8 + (lane & 3) * 2;
            float2 bb = make_float2(0.f, 0.f);
            if (BIAS) bb = *(const float2*)(bias + c);
            int r0 = node0 + mrow0 + i * 16 + (lane >> 2);
            int r1 = r0 + 8;
            if (OUT16) {
                __half* o = (__half*)outv;
                if (r0 < NN)
                    *(__half2*)(o + (size_t)r0 * NF + c) =
                        __floats2half2_rn(acc[i][j][0] + bb.x, acc[i][j][1] + bb.y);
                if (r1 < NN)
                    *(__half2*)(o + (size_t)r1 * NF + c) =
                        __floats2half2_rn(acc[i][j][2] + bb.x, acc[i][j][3] + bb.y);
            } else {
                float* o = (float*)outv;
                if (r0 < NN)
                    *(float2*)(o + (size_t)r0 * NF + c) =
                        make_float2(acc[i][j][0] + bb.x, acc[i][j][1] + bb.y);
                if (r1 < NN)
                    *(float2*)(o + (size_t)r1 * NF + c) =
                        make_float2(acc[i][j][2] + bb.x, acc[i][j][3] + bb.y);
            }
        }
    }
}

// ---------------- aggregation kernels (one warp per node) -------------------
__global__ void k_agg64(float* __restrict__ out) {
    int n = (blockIdx.x * blockDim.x + threadIdx.x) >> 5;
    if (n >= NN) return;
    int lane = threadIdx.x & 31;
    int beg = g_rowptr[n], end = g_rowptr[n + 1];
    const __half2* X = (const __half2*)g_x16;
    float2 acc = make_float2(0.f, 0.f);
    int j = beg;
    for (; j + 3 < end; j += 4) {
        int   s0 = g_csr_src[j],   s1 = g_csr_src[j+1],
              s2 = g_csr_src[j+2], s3 = g_csr_src[j+3];
        float w0 = g_csr_w[j],   w1 = g_csr_w[j+1],
              w2 = g_csr_w[j+2], w3 = g_csr_w[j+3];
        float2 v0 = __half22float2(__ldg(X + s0 * 32 + lane));
        float2 v1 = __half22float2(__ldg(X + s1 * 32 + lane));
        float2 v2 = __half22float2(__ldg(X + s2 * 32 + lane));
        float2 v3 = __half22float2(__ldg(X + s3 * 32 + lane));
        acc.x += w0*v0.x + w1*v1.x + w2*v2.x + w3*v3.x;
        acc.y += w0*v0.y + w1*v1.y + w2*v2.y + w3*v3.y;
    }
    for (; j < end; j++) {
        int s = g_csr_src[j]; float w = g_csr_w[j];
        float2 v = __half22float2(__ldg(X + s * 32 + lane));
        acc.x += w * v.x; acc.y += w * v.y;
    }
    *(float2*)(out + n * 64 + lane * 2) = acc;
}

__global__ void k_agg128(const __half* __restrict__ T, const float* __restrict__ bias,
                         float* __restrict__ out) {
    int n = (blockIdx.x * blockDim.x + threadIdx.x) >> 5;
    if (n >= NN) return;
    int lane = threadIdx.x & 31;
    int beg = g_rowptr[n], end = g_rowptr[n + 1];
    const uint2* Tv = (const uint2*)T;
    float4 acc = make_float4(0.f, 0.f, 0.f, 0.f);
    int j = beg;
    for (; j + 3 < end; j += 4) {
        int   s0 = g_csr_src[j],   s1 = g_csr_src[j+1],
              s2 = g_csr_src[j+2], s3 = g_csr_src[j+3];
        float w0 = g_csr_w[j],   w1 = g_csr_w[j+1],
              w2 = g_csr_w[j+2], w3 = g_csr_w[j+3];
        uint2 p0 = __ldg(Tv + s0 * 32 + lane);
        uint2 p1 = __ldg(Tv + s1 * 32 + lane);
        uint2 p2 = __ldg(Tv + s2 * 32 + lane);
        uint2 p3 = __ldg(Tv + s3 * 32 + lane);
        float2 a0 = h2f2(p0.x), b0 = h2f2(p0.y);
        float2 a1 = h2f2(p1.x), b1 = h2f2(p1.y);
        float2 a2 = h2f2(p2.x), b2 = h2f2(p2.y);
        float2 a3 = h2f2(p3.x), b3 = h2f2(p3.y);
        acc.x += w0*a0.x + w1*a1.x + w2*a2.x + w3*a3.x;
        acc.y += w0*a0.y + w1*a1.y + w2*a2.y + w3*a3.y;
        acc.z += w0*b0.x + w1*b1.x + w2*b2.x + w3*b3.x;
        acc.w += w0*b0.y + w1*b1.y + w2*b2.y + w3*b3.y;
    }
    for (; j < end; j++) {
        int s = g_csr_src[j]; float w = g_csr_w[j];
        uint2 p = __ldg(Tv + s * 32 + lane);
        float2 a = h2f2(p.x), b = h2f2(p.y);
        acc.x += w*a.x; acc.y += w*a.y; acc.z += w*b.x; acc.w += w*b.y;
    }
    float4 bb = __ldg((const float4*)(bias + lane * 4));
    acc.x += bb.x; acc.y += bb.y; acc.z += bb.z; acc.w += bb.w;
    *(float4*)(out + n * NF + lane * 4) = acc;
}

__global__ void k_agg3(const float* __restrict__ T, const float* __restrict__ bout,
                       float* __restrict__ out) {
    int n = (blockIdx.x * blockDim.x + threadIdx.x) >> 5;
    if (n >= NN) return;
    int lane = threadIdx.x & 31;
    int beg = g_rowptr[n], end = g_rowptr[n + 1];
    float a0 = 0.f, a1 = 0.f, a2 = 0.f;
    for (int j = beg + lane; j < end; j += 32) {
        int s = g_csr_src[j]; float w = g_csr_w[j];
        a0 += w * __ldg(T + s * 3 + 0);
        a1 += w * __ldg(T + s * 3 + 1);
        a2 += w * __ldg(T + s * 3 + 2);
    }
    #pragma unroll
    for (int o = 16; o > 0; o >>= 1) {
        a0 += __shfl_down_sync(0xffffffffu, a0, o);
        a1 += __shfl_down_sync(0xffffffffu, a1, o);
        a2 += __shfl_down_sync(0xffffffffu, a2, o);
    }
    if (lane == 0) {
        out[n * 3 + 0] = tanhf(a0 + __ldg(bout + 0)) * 0.5f;
        out[n * 3 + 1] = tanhf(a1 + __ldg(bout + 1)) * 0.5f;
        out[n * 3 + 2] = tanhf(a2 + __ldg(bout + 2)) * 0.5f;
    }
}

// ---------------- output head -----------------------------------------------
__global__ void k_gemm3(const float* __restrict__ H, const float* __restrict__ W,
                        float* __restrict__ out) {
    int n = (blockIdx.x * blockDim.x + threadIdx.x) >> 5;
    if (n >= NN) return;
    int lane = threadIdx.x & 31;
    float4 h = *(const float4*)(H + (size_t)n * NF + lane * 4);
    h.x = h.x > 0.f ? h.x : h.x * SLOPE;
    h.y = h.y > 0.f ? h.y : h.y * SLOPE;
    h.z = h.z > 0.f ? h.z : h.z * SLOPE;
    h.w = h.w > 0.f ? h.w : h.w * SLOPE;
    float hv[4] = {h.x, h.y, h.z, h.w};
    float a0 = 0.f, a1 = 0.f, a2 = 0.f;
    #pragma unroll
    for (int j = 0; j < 4; j++) {
        int k = lane * 4 + j;
        a0 += hv[j] * __ldg(W + k * 3 + 0);
        a1 += hv[j] * __ldg(W + k * 3 + 1);
        a2 += hv[j] * __ldg(W + k * 3 + 2);
    }
    #pragma unroll
    for (int o = 16; o > 0; o >>= 1) {
        a0 += __shfl_down_sync(0xffffffffu, a0, o);
        a1 += __shfl_down_sync(0xffffffffu, a1, o);
        a2 += __shfl_down_sync(0xffffffffu, a2, o);
    }
    if (lane == 0) {
        out[n * 3 + 0] = a0;
        out[n * 3 + 1] = a1;
        out[n * 3 + 2] = a2;
    }
}

// ---------------- launch -----------------------------------------------------
extern "C" void kernel_launch(void* const* d_in, const int* in_sizes, int n_in,
                              void* d_out, int out_size) {
    const float* x    = (const float*)d_in[0];
    const void*  ei   = d_in[1];
    const float* W0   = (const float*)d_in[2];
    const float* b0   = (const float*)d_in[3];
    const float* Wh   = (const float*)d_in[4];
    const float* bh   = (const float*)d_in[5];
    const float* Wout = (const float*)d_in[6];
    const float* bout = (const float*)d_in[7];
    float* out = (float*)d_out;

    void *pA, *pB, *pM, *pWh, *pW0;
    cudaGetSymbolAddress(&pA, g_bufA);
    cudaGetSymbolAddress(&pB, g_bufB);
    cudaGetSymbolAddress(&pM, g_bufM);
    cudaGetSymbolAddress(&pWh, g_wimg_h);
    cudaGetSymbolAddress(&pW0, g_wimg_0);
    float* A = (float*)pA;
    float* B = (float*)pB;
    __half* M16 = (__half*)pM;
    const unsigned short* WIH = (const unsigned short*)pWh;
    const unsigned short* WI0 = (const unsigned short*)pW0;

    const int SM128 = 3 * 128 * 128 * 2;  // 96 KB (A + Wh + Wl)
    const int SM64  = 3 * 128 * 64 * 2;   // 48 KB
    cudaFuncSetAttribute((const void*)k_gemm_mma<128, true, false, true>,
                         cudaFuncAttributeMaxDynamicSharedMemorySize, SM128);
    cudaFuncSetAttribute((const void*)k_gemm_mma<64, false, true, false>,
                         cudaFuncAttributeMaxDynamicSharedMemorySize, SM64);

    const int scanBlocks = (NN + 255) / 256;  // 118

    k_prep<<<(PREP_ITEMS + 255) / 256, 256>>>(x, Wh, W0);
    k_count<<<(EE + 255) / 256, 256>>>(ei);
    k_scanA<<<scanBlocks, 256>>>();
    k_scanC<<<scanBlocks, 256>>>(scanBlocks);
    k_fill<<<(EN + 255) / 256, 256>>>(ei);

    const int warpBlocks = (NN * 32 + 255) / 256;   // one warp per node
    const int tcBlocks   = (NN + 127) / 128;        // 235 single-tile blocks

    // layer 0:  B = (A x) @ W0 + b0
    k_agg64<<<warpBlocks, 256>>>(A);
    k_gemm_mma<64, false, true, false><<<tcBlocks, 256, SM64>>>(A, WI0, b0, B);

    // 6 hidden layers: M16 = leaky(h)@Wh[i] (fp16);  h = A·M16 + bh[i] (fp32, in B)
    for (int i = 0; i < 6; i++) {
        k_gemm_mma<128, true, false, true><<<tcBlocks, 256, SM128>>>(
            B, WIH + (size_t)i * 32768, nullptr, M16);
        k_agg128<<<warpBlocks, 256>>>(M16, bh + (size_t)i * NF, B);
    }

    // output: out = tanh( A (leaky(h) @ Wout) + bout ) * 0.5
    k_gemm3<<<warpBlocks, 256>>>(B, Wout, A);
    k_agg3<<<warpBlocks, 256>>>(A, bout, out);
}

// round 11
// speedup vs baseline: 2.4556x; 1.0189x over previous
#include <cuda_runtime.h>
#include <cuda_fp16.h>
#include <math.h>
#include <stdint.h>

#define NN 30000
#define EE 480000
#define EN (EE + NN)
#define NF 128
#define SLOPE 0.02f

// ---------------- scratch (device globals; no allocation allowed) ----------
__device__ int   g_cnt[NN];
__device__ float g_dinv[NN];
__device__ int   g_rowptr[NN + 1];
__device__ int   g_fill[NN];
__device__ int   g_csr_src[EN];
__device__ float g_csr_w[EN];
__device__ float g_bufA[NN * NF];    // fp32 scratch (agg64 out, head proj)
__device__ __half g_bufH[NN * NF];   // fp16 hidden state (pre-activated)
__device__ __half g_bufM[NN * NF];   // fp16 message buffer (gathered operand)
__device__ __half g_x16[NN * 64];    // fp16 copy of input x
__device__ int   g_bsum[128];
// pre-imaged weights (exact swizzled smem byte layout), fp16 hi/lo planes.
__device__ unsigned short g_wimg_h[6 * 2 * 16384];
__device__ unsigned short g_wimg_0[2 * 8192];

// ---------------- mma/ldmatrix helpers (plain sm_103-safe PTX) -------------
__device__ __forceinline__ uint32_t smem_u32(const void* p) {
    uint32_t a;
    asm("{ .reg .u64 t; cvta.to.shared.u64 t, %1; cvt.u32.u64 %0, t; }"
        : "=r"(a) : "l"(p));
    return a;
}

#define LDSM_X4(r0, r1, r2, r3, addr) \
    asm volatile("ldmatrix.sync.aligned.m8n8.x4.shared.b16 {%0,%1,%2,%3}, [%4];" \
                 : "=r"(r0), "=r"(r1), "=r"(r2), "=r"(r3) : "r"(addr))

#define MMA16816F16(d, a, b) \
    asm volatile("mma.sync.aligned.m16n8k16.row.col.f32.f16.f16.f32 " \
                 "{%0,%1,%2,%3}, {%4,%5,%6,%7}, {%8,%9}, {%0,%1,%2,%3};" \
                 : "+f"((d)[0]), "+f"((d)[1]), "+f"((d)[2]), "+f"((d)[3]) \
                 : "r"((a)[0]), "r"((a)[1]), "r"((a)[2]), "r"((a)[3]), \
                   "r"((b)[0]), "r"((b)[1]))

__device__ __forceinline__ uint32_t packh2(float a, float b) {
    __half2 h = __floats2half2_rn(a, b);
    return *(uint32_t*)&h;
}

__device__ __forceinline__ float2 h2f2(uint32_t h) {
    __half2 v = *(__half2*)&h;
    return __half22float2(v);
}

__device__ __forceinline__ float lrelu(float v) {
    return v > 0.f ? v : v * SLOPE;
}

// per-block inline dtype sniff: int64 edges < 2^31 => odd words of first 128 are 0
__device__ __forceinline__ int sniff_is64(const void* ei, int* s_flag) {
    if (threadIdx.x < 32) {
        const unsigned* w = (const unsigned*)ei;
        unsigned bad = 0;
        for (int i = threadIdx.x; i < 128; i += 32) bad |= w[2 * i + 1];
        #pragma unroll
        for (int o = 16; o > 0; o >>= 1) bad |= __shfl_xor_sync(0xffffffffu, bad, o);
        if (threadIdx.x == 0) *s_flag = (bad == 0u);
    }
    __syncthreads();
    return *s_flag;
}

__device__ __forceinline__ int edge_at2(const void* ei, int idx, int is64) {
    return is64 ? (int)((const long long*)ei)[idx] : ((const int*)ei)[idx];
}

// ---------------- merged prep: cnt init + x16 + weight images ---------------
__global__ void k_prep(const float* __restrict__ x, const float* __restrict__ Wh,
                       const float* __restrict__ W0) {
    int idx = blockIdx.x * 256 + threadIdx.x;
    if (idx < NN * 32) {
        float2 v = __ldg((const float2*)(x + 2 * idx));
        ((__half2*)g_x16)[idx] = __floats2half2_rn(v.x, v.y);
        return;
    }
    idx -= NN * 32;
    if (idx < 6 * 128 * 16) {
        int i = idx / (128 * 16);
        int r = idx % (128 * 16);
        int f = r / 16;
        int chunk = r % 16;
        const float* W = Wh + (size_t)i * 16384;
        float v[8], h[8];
        #pragma unroll
        for (int j = 0; j < 8; j++) {
            v[j] = W[(chunk * 8 + j) * 128 + f];
            h[j] = __half2float(__float2half_rn(v[j]));
        }
        uint4 hi = make_uint4(packh2(h[0], h[1]), packh2(h[2], h[3]),
                              packh2(h[4], h[5]), packh2(h[6], h[7]));
        uint4 lo = make_uint4(packh2(v[0]-h[0], v[1]-h[1]), packh2(v[2]-h[2], v[3]-h[3]),
                              packh2(v[4]-h[4], v[5]-h[5]), packh2(v[6]-h[6], v[7]-h[7]));
        int off = f * 256 + ((chunk ^ (f & 7)) << 4);
        char* base = (char*)g_wimg_h + (size_t)i * 65536;
        *(uint4*)(base + off)         = hi;
        *(uint4*)(base + 32768 + off) = lo;
        return;
    }
    idx -= 6 * 128 * 16;
    if (idx < 128 * 8) {
        int f = idx / 8;
        int chunk = idx % 8;
        float v[8], h[8];
        #pragma unroll
        for (int j = 0; j < 8; j++) {
            v[j] = W0[(chunk * 8 + j) * 128 + f];
            h[j] = __half2float(__float2half_rn(v[j]));
        }
        uint4 hi = make_uint4(packh2(h[0], h[1]), packh2(h[2], h[3]),
                              packh2(h[4], h[5]), packh2(h[6], h[7]));
        uint4 lo = make_uint4(packh2(v[0]-h[0], v[1]-h[1]), packh2(v[2]-h[2], v[3]-h[3]),
                              packh2(v[4]-h[4], v[5]-h[5]), packh2(v[6]-h[6], v[7]-h[7]));
        int off = f * 128 + ((chunk ^ (f & 7)) << 4);
        char* base = (char*)g_wimg_0;
        *(uint4*)(base + off)         = hi;
        *(uint4*)(base + 16384 + off) = lo;
        return;
    }
    idx -= 128 * 8;
    if (idx < NN) g_cnt[idx] = 1;   // self-loop
}
#define PREP_ITEMS (NN * 32 + 6 * 128 * 16 + 128 * 8 + NN)

// ---------------- graph preprocessing ---------------------------------------
__global__ void k_count(const void* __restrict__ ei) {
    __shared__ int s64;
    int is64 = sniff_is64(ei, &s64);
    int e = blockIdx.x * blockDim.x + threadIdx.x;
    if (e < EE) atomicAdd(&g_cnt[edge_at2(ei, EE + e, is64)], 1);
}

__global__ void k_scanA() {
    int i = blockIdx.x * 256 + threadIdx.x;
    int v = (i < NN) ? g_cnt[i] : 0;
    __shared__ int sh[8];
    #pragma unroll
    for (int o = 16; o > 0; o >>= 1) v += __shfl_down_sync(0xffffffffu, v, o);
    if ((threadIdx.x & 31) == 0) sh[threadIdx.x >> 5] = v;
    __syncthreads();
    if (threadIdx.x < 8) {
        int t = sh[threadIdx.x];
        #pragma unroll
        for (int o = 4; o > 0; o >>= 1) t += __shfl_down_sync(0xffu, t, o);
        if (threadIdx.x == 0) g_bsum[blockIdx.x] = t;
    }
}

__global__ void k_scanC(int nblk) {
    __shared__ int sh[256];
    __shared__ int sbs[128];
    __shared__ int s_base;
    const int tid = threadIdx.x;
    const int bid = blockIdx.x;
    if (tid < nblk) sbs[tid] = g_bsum[tid];
    __syncthreads();
    if (tid < 32) {
        int p = 0;
        for (int j = tid; j < bid; j += 32) p += sbs[j];
        #pragma unroll
        for (int o = 16; o > 0; o >>= 1) p += __shfl_down_sync(0xffffffffu, p, o);
        if (tid == 0) s_base = p;
    }
    int i = bid * 256 + tid;
    int v = (i < NN) ? g_cnt[i] : 0;
    sh[tid] = v;
    __syncthreads();
    #pragma unroll
    for (int d = 1; d < 256; d <<= 1) {
        int a = (tid >= d) ? sh[tid - d] : 0;
        __syncthreads();
        sh[tid] += a;
        __syncthreads();
    }
    if (i < NN) {
        int excl = sh[tid] - v + s_base;
        g_rowptr[i] = excl;
        g_fill[i]   = excl;
        g_dinv[i]   = rsqrtf((float)v);
        if (i == NN - 1) g_rowptr[NN] = excl + v;
    }
}

__global__ void k_fill(const void* __restrict__ ei) {
    __shared__ int s64;
    int is64 = sniff_is64(ei, &s64);
    int e = blockIdx.x * blockDim.x + threadIdx.x;
    if (e < EE) {
        int s = edge_at2(ei, e, is64);
        int d = edge_at2(ei, EE + e, is64);
        int pos = atomicAdd(&g_fill[d], 1);
        g_csr_src[pos] = s;
        g_csr_w[pos]   = g_dinv[s] * g_dinv[d];
    } else if (e < EN) {
        int i = e - EE;
        int pos = atomicAdd(&g_fill[i], 1);
        float di = g_dinv[i];
        g_csr_src[pos] = i;
        g_csr_w[pos]   = di * di;
    }
}

// ---------------- tensor GEMM: 128 nodes x 128 outs per block ---------------
// A = fp16 (no split), W = fp16 hi/lo planes: D = A*Wh + A*Wl (fp32 accum).
// IN16: input rows already fp16 (pre-activated) -> staging is a swizzled copy.
// OUTACT/BIAS: epilogue bias + leaky; output always fp16.
template<int K, bool IN16, bool BIAS, bool OUTACT>
__global__ void __launch_bounds__(256) k_gemm_mma(const void* __restrict__ Hin,
                                                  const unsigned short* __restrict__ Wimg,
                                                  const float* __restrict__ bias,
                                                  __half* __restrict__ outp) {
    extern __shared__ char smem[];
    constexpr int PITCH  = K * 2;
    constexpr int PBYTES = 128 * PITCH;
    constexpr int OFF_A  = 0;
    constexpr int OFF_BH = PBYTES;
    constexpr int OFF_BL = 2 * PBYTES;
    const int tid  = threadIdx.x;
    const int wid  = tid >> 5;
    const int lane = tid & 31;
    const int node0 = blockIdx.x * 128;
    const uint32_t sb = smem_u32(smem);

    // stage W (hi + lo planes, contiguous in gmem image)
    {
        const uint4* src = (const uint4*)Wimg;
        uint4* dst = (uint4*)(smem + OFF_BH);
        #pragma unroll
        for (int i = tid; i < 2 * PBYTES / 16; i += 256) dst[i] = src[i];
    }
    // stage A: 128 rows x K, swizzled 16B chunks (8 values per chunk)
    {
        constexpr int NCH = K / 8;
        #pragma unroll
        for (int idx = tid; idx < 128 * NCH; idx += 256) {
            int row = idx / NCH;
            int chunk = idx % NCH;
            int node = node0 + row;
            uint4 a16 = make_uint4(0u, 0u, 0u, 0u);
            if (IN16) {
                if (node < NN)
                    a16 = __ldg((const uint4*)Hin + (size_t)node * NCH + chunk);
            } else {
                const float* H = (const float*)Hin;
                float4 v0 = make_float4(0.f, 0.f, 0.f, 0.f), v1 = v0;
                if (node < NN) {
                    v0 = __ldg((const float4*)(H + (size_t)node * K + chunk * 8));
                    v1 = __ldg((const float4*)(H + (size_t)node * K + chunk * 8 + 4));
                }
                a16 = make_uint4(packh2(v0.x, v0.y), packh2(v0.z, v0.w),
                                 packh2(v1.x, v1.y), packh2(v1.z, v1.w));
            }
            int off = row * PITCH + ((chunk ^ (row & 7)) << 4);
            *(uint4*)(smem + OFF_A + off) = a16;
        }
    }
    __syncthreads();

    const int mrow0 = (wid & 3) * 32;
    const int ncol0 = (wid >> 2) * 64;
    float acc[2][8][4] = {};
    const uint32_t aB = sb + OFF_A;
    const uint32_t bOff[2] = {sb + OFF_BH, sb + OFF_BL};

    #pragma unroll
    for (int t = 0; t < 2; t++) {
        const uint32_t bB = bOff[t];
        #pragma unroll
        for (int ks = 0; ks < K / 16; ks++) {
            uint32_t a[2][4], b[8][2];
            #pragma unroll
            for (int i = 0; i < 2; i++) {
                int row = mrow0 + i * 16 + (lane & 15);
                int chunk = ks * 2 + (lane >> 4);
                uint32_t addr = aB + row * PITCH + ((chunk ^ (row & 7)) << 4);
                LDSM_X4(a[i][0], a[i][1], a[i][2], a[i][3], addr);
            }
            #pragma unroll
            for (int p = 0; p < 4; p++) {
                int nrow = ncol0 + p * 16 + (lane >> 4) * 8 + (lane & 7);
                int chunk = ks * 2 + ((lane >> 3) & 1);
                uint32_t addr = bB + nrow * PITCH + ((chunk ^ (nrow & 7)) << 4);
                LDSM_X4(b[2*p][0], b[2*p][1], b[2*p+1][0], b[2*p+1][1], addr);
            }
            #pragma unroll
            for (int i = 0; i < 2; i++)
                #pragma unroll
                for (int j = 0; j < 8; j++)
                    MMA16816F16(acc[i][j], a[i], b[j]);
        }
    }

    #pragma unroll
    for (int i = 0; i < 2; i++) {
        #pragma unroll
        for (int j = 0; j < 8; j++) {
            int c = ncol0 + j * 8 + (lane & 3) * 2;
            float2 bb = make_float2(0.f, 0.f);
            if (BIAS) bb = *(const float2*)(bias + c);
            float e0 = acc[i][j][0] + bb.x, e1 = acc[i][j][1] + bb.y;
            float e2 = acc[i][j][2] + bb.x, e3 = acc[i][j][3] + bb.y;
            if (OUTACT) { e0 = lrelu(e0); e1 = lrelu(e1); e2 = lrelu(e2); e3 = lrelu(e3); }
            int r0 = node0 + mrow0 + i * 16 + (lane >> 2);
            int r1 = r0 + 8;
            if (r0 < NN)
                *(__half2*)(outp + (size_t)r0 * NF + c) = __floats2half2_rn(e0, e1);
            if (r1 < NN)
                *(__half2*)(outp + (size_t)r1 * NF + c) = __floats2half2_rn(e2, e3);
        }
    }
}

// ---------------- aggregation kernels (one warp per node) -------------------
__global__ void k_agg64(float* __restrict__ out) {
    int n = (blockIdx.x * blockDim.x + threadIdx.x) >> 5;
    if (n >= NN) return;
    int lane = threadIdx.x & 31;
    int beg = g_rowptr[n], end = g_rowptr[n + 1];
    const __half2* X = (const __half2*)g_x16;
    float2 acc = make_float2(0.f, 0.f);
    int j = beg;
    for (; j + 3 < end; j += 4) {
        int   s0 = g_csr_src[j],   s1 = g_csr_src[j+1],
              s2 = g_csr_src[j+2], s3 = g_csr_src[j+3];
        float w0 = g_csr_w[j],   w1 = g_csr_w[j+1],
              w2 = g_csr_w[j+2], w3 = g_csr_w[j+3];
        float2 v0 = __half22float2(__ldg(X + s0 * 32 + lane));
        float2 v1 = __half22float2(__ldg(X + s1 * 32 + lane));
        float2 v2 = __half22float2(__ldg(X + s2 * 32 + lane));
        float2 v3 = __half22float2(__ldg(X + s3 * 32 + lane));
        acc.x += w0*v0.x + w1*v1.x + w2*v2.x + w3*v3.x;
        acc.y += w0*v0.y + w1*v1.y + w2*v2.y + w3*v3.y;
    }
    for (; j < end; j++) {
        int s = g_csr_src[j]; float w = g_csr_w[j];
        float2 v = __half22float2(__ldg(X + s * 32 + lane));
        acc.x += w * v.x; acc.y += w * v.y;
    }
    *(float2*)(out + n * 64 + lane * 2) = acc;
}

// 128-dim fp16 gather; epilogue: +bias, leaky, store fp16 hidden state
__global__ void k_agg128(const __half* __restrict__ T, const float* __restrict__ bias,
                         __half* __restrict__ out) {
    int n = (blockIdx.x * blockDim.x + threadIdx.x) >> 5;
    if (n >= NN) return;
    int lane = threadIdx.x & 31;
    int beg = g_rowptr[n], end = g_rowptr[n + 1];
    const uint2* Tv = (const uint2*)T;
    float4 acc = make_float4(0.f, 0.f, 0.f, 0.f);
    int j = beg;
    for (; j + 3 < end; j += 4) {
        int   s0 = g_csr_src[j],   s1 = g_csr_src[j+1],
              s2 = g_csr_src[j+2], s3 = g_csr_src[j+3];
        float w0 = g_csr_w[j],   w1 = g_csr_w[j+1],
              w2 = g_csr_w[j+2], w3 = g_csr_w[j+3];
        uint2 p0 = __ldg(Tv + s0 * 32 + lane);
        uint2 p1 = __ldg(Tv + s1 * 32 + lane);
        uint2 p2 = __ldg(Tv + s2 * 32 + lane);
        uint2 p3 = __ldg(Tv + s3 * 32 + lane);
        float2 a0 = h2f2(p0.x), b0 = h2f2(p0.y);
        float2 a1 = h2f2(p1.x), b1 = h2f2(p1.y);
        float2 a2 = h2f2(p2.x), b2 = h2f2(p2.y);
        float2 a3 = h2f2(p3.x), b3 = h2f2(p3.y);
        acc.x += w0*a0.x + w1*a1.x + w2*a2.x + w3*a3.x;
        acc.y += w0*a0.y + w1*a1.y + w2*a2.y + w3*a3.y;
        acc.z += w0*b0.x + w1*b1.x + w2*b2.x + w3*b3.x;
        acc.w += w0*b0.y + w1*b1.y + w2*b2.y + w3*b3.y;
    }
    for (; j < end; j++) {
        int s = g_csr_src[j]; float w = g_csr_w[j];
        uint2 p = __ldg(Tv + s * 32 + lane);
        float2 a = h2f2(p.x), b = h2f2(p.y);
        acc.x += w*a.x; acc.y += w*a.y; acc.z += w*b.x; acc.w += w*b.y;
    }
    float4 bb = __ldg((const float4*)(bias + lane * 4));
    float e0 = lrelu(acc.x + bb.x), e1 = lrelu(acc.y + bb.y);
    float e2 = lrelu(acc.z + bb.z), e3 = lrelu(acc.w + bb.w);
    uint2 pk = make_uint2(packh2(e0, e1), packh2(e2, e3));
    *(uint2*)(out + (size_t)n * NF + lane * 4) = pk;
}

__global__ void k_agg3(const float* __restrict__ T, const float* __restrict__ bout,
                       float* __restrict__ out) {
    int n = (blockIdx.x * blockDim.x + threadIdx.x) >> 5;
    if (n >= NN) return;
    int lane = threadIdx.x & 31;
    int beg = g_rowptr[n], end = g_rowptr[n + 1];
    float a0 = 0.f, a1 = 0.f, a2 = 0.f;
    for (int j = beg + lane; j < end; j += 32) {
        int s = g_csr_src[j]; float w = g_csr_w[j];
        a0 += w * __ldg(T + s * 3 + 0);
        a1 += w * __ldg(T + s * 3 + 1);
        a2 += w * __ldg(T + s * 3 + 2);
    }
    #pragma unroll
    for (int o = 16; o > 0; o >>= 1) {
        a0 += __shfl_down_sync(0xffffffffu, a0, o);
        a1 += __shfl_down_sync(0xffffffffu, a1, o);
        a2 += __shfl_down_sync(0xffffffffu, a2, o);
    }
    if (lane == 0) {
        out[n * 3 + 0] = tanhf(a0 + __ldg(bout + 0)) * 0.5f;
        out[n * 3 + 1] = tanhf(a1 + __ldg(bout + 1)) * 0.5f;
        out[n * 3 + 2] = tanhf(a2 + __ldg(bout + 2)) * 0.5f;
    }
}

// ---------------- output head: P = H16 @ Wout (H16 already activated) -------
__global__ void k_gemm3(const __half* __restrict__ H, const float* __restrict__ W,
                        float* __restrict__ out) {
    int n = (blockIdx.x * blockDim.x + threadIdx.x) >> 5;
    if (n >= NN) return;
    int lane = threadIdx.x & 31;
    uint2 p = __ldg((const uint2*)H + (size_t)n * 32 + lane);
    float2 ha = h2f2(p.x), hb = h2f2(p.y);
    float hv[4] = {ha.x, ha.y, hb.x, hb.y};
    float a0 = 0.f, a1 = 0.f, a2 = 0.f;
    #pragma unroll
    for (int j = 0; j < 4; j++) {
        int k = lane * 4 + j;
        a0 += hv[j] * __ldg(W + k * 3 + 0);
        a1 += hv[j] * __ldg(W + k * 3 + 1);
        a2 += hv[j] * __ldg(W + k * 3 + 2);
    }
    #pragma unroll
    for (int o = 16; o > 0; o >>= 1) {
        a0 += __shfl_down_sync(0xffffffffu, a0, o);
        a1 += __shfl_down_sync(0xffffffffu, a1, o);
        a2 += __shfl_down_sync(0xffffffffu, a2, o);
    }
    if (lane == 0) {
        out[n * 3 + 0] = a0;
        out[n * 3 + 1] = a1;
        out[n * 3 + 2] = a2;
    }
}

// ---------------- launch -----------------------------------------------------
extern "C" void kernel_launch(void* const* d_in, const int* in_sizes, int n_in,
                              void* d_out, int out_size) {
    const float* x    = (const float*)d_in[0];
    const void*  ei   = d_in[1];
    const float* W0   = (const float*)d_in[2];
    const float* b0   = (const float*)d_in[3];
    const float* Wh   = (const float*)d_in[4];
    const float* bh   = (const float*)d_in[5];
    const float* Wout = (const float*)d_in[6];
    const float* bout = (const float*)d_in[7];
    float* out = (float*)d_out;

    void *pA, *pH, *pM, *pWh, *pW0;
    cudaGetSymbolAddress(&pA, g_bufA);
    cudaGetSymbolAddress(&pH, g_bufH);
    cudaGetSymbolAddress(&pM, g_bufM);
    cudaGetSymbolAddress(&pWh, g_wimg_h);
    cudaGetSymbolAddress(&pW0, g_wimg_0);
    float* A = (float*)pA;
    __half* H16 = (__half*)pH;
    __half* M16 = (__half*)pM;
    const unsigned short* WIH = (const unsigned short*)pWh;
    const unsigned short* WI0 = (const unsigned short*)pW0;

    const int SM128 = 3 * 128 * 128 * 2;  // 96 KB (A + Wh + Wl)
    const int SM64  = 3 * 128 * 64 * 2;   // 48 KB
    cudaFuncSetAttribute((const void*)k_gemm_mma<128, true, false, false>,
                         cudaFuncAttributeMaxDynamicSharedMemorySize, SM128);
    cudaFuncSetAttribute((const void*)k_gemm_mma<64, false, true, true>,
                         cudaFuncAttributeMaxDynamicSharedMemorySize, SM64);

    const int scanBlocks = (NN + 255) / 256;  // 118

    k_prep<<<(PREP_ITEMS + 255) / 256, 256>>>(x, Wh, W0);
    k_count<<<(EE + 255) / 256, 256>>>(ei);
    k_scanA<<<scanBlocks, 256>>>();
    k_scanC<<<scanBlocks, 256>>>(scanBlocks);
    k_fill<<<(EN + 255) / 256, 256>>>(ei);

    const int warpBlocks = (NN * 32 + 255) / 256;   // one warp per node
    const int tcBlocks   = (NN + 127) / 128;        // 235

    // layer 0:  H16 = leaky( (A x) @ W0 + b0 )   (fp16, pre-activated)
    k_agg64<<<warpBlocks, 256>>>(A);
    k_gemm_mma<64, false, true, true><<<tcBlocks, 256, SM64>>>(A, WI0, b0, H16);

    // 6 hidden layers: M16 = H16 @ Wh[i];  H16 = leaky( A·M16 + bh[i] )  (fp16)
    for (int i = 0; i < 6; i++) {
        k_gemm_mma<128, true, false, false><<<tcBlocks, 256, SM128>>>(
            H16, WIH + (size_t)i * 32768, nullptr, M16);
        k_agg128<<<warpBlocks, 256>>>(M16, bh + (size_t)i * NF, H16);
    }

    // output: out = tanh( A (H16 @ Wout) + bout ) * 0.5
    k_gemm3<<<warpBlocks, 256>>>(H16, Wout, A);
    k_agg3<<<warpBlocks, 256>>>(A, bout, out);
}